// round 5
// baseline (speedup 1.0000x reference)
#include <cuda_runtime.h>
#include <cuda_bf16.h>
#include <cstdint>
#include <cstddef>

#define N_NODES 100000
#define M_PAD   100096
#define N_EDGES 300000
#define N_GRAPHS 2048

// ---------------- scratch (no allocations allowed) ----------------
__device__ __align__(256) float g_h[(size_t)N_NODES * 512];
__device__ __align__(256) float g_z[(size_t)N_NODES * 256];          // agg buffer
__device__ __align__(256) __nv_bfloat16 g_thi[(size_t)M_PAD * 512];  // t hi
__device__ __align__(256) __nv_bfloat16 g_tlo[(size_t)M_PAD * 512];  // t lo
__device__ __align__(256) __nv_bfloat16 g_whi[622592];
__device__ __align__(256) __nv_bfloat16 g_wlo[622592];

// ---------------- helpers ----------------
__device__ __forceinline__ uint32_t smem_u32(const void* p) {
    uint32_t a;
    asm("{ .reg .u64 t; cvta.to.shared.u64 t, %1; cvt.u32.u64 %0, t; }"
        : "=r"(a) : "l"(p));
    return a;
}

#define LDM4(r, addr)                                                         \
    asm volatile("ldmatrix.sync.aligned.m8n8.x4.shared.b16 {%0,%1,%2,%3}, [%4];" \
                 : "=r"((r)[0]), "=r"((r)[1]), "=r"((r)[2]), "=r"((r)[3])     \
                 : "r"(addr))

#define MMA16816(c, a, b0, b1)                                                \
    asm volatile("mma.sync.aligned.m16n8k16.row.col.f32.bf16.bf16.f32 "        \
                 "{%0,%1,%2,%3}, {%4,%5,%6,%7}, {%8,%9}, {%0,%1,%2,%3};"       \
                 : "+f"((c)[0]), "+f"((c)[1]), "+f"((c)[2]), "+f"((c)[3])      \
                 : "r"((a)[0]), "r"((a)[1]), "r"((a)[2]), "r"((a)[3]),         \
                   "r"(b0), "r"(b1))

#define CP16(saddr, gaddr)                                                    \
    asm volatile("cp.async.cg.shared.global [%0], [%1], 16;" ::               \
                 "r"(saddr), "l"(gaddr))

// ---------------- weight prep: fp32 [K][N] -> bf16 hi/lo [N][K] ----------------
__global__ void prep_w(const float* __restrict__ W, __nv_bfloat16* __restrict__ hi,
                       __nv_bfloat16* __restrict__ lo, int K, int N) {
    int i = blockIdx.x * blockDim.x + threadIdx.x;
    if (i >= K * N) return;
    int k = i / N, n = i % N;
    float x = W[i];
    __nv_bfloat16 h = __float2bfloat16(x);
    float r = x - __bfloat162float(h);
    hi[(size_t)n * K + k] = h;
    lo[(size_t)n * K + k] = __float2bfloat16(r);
}

// ---------------- node feature embed: h = x @ W_embed + b ----------------
__global__ __launch_bounds__(256)
void embed_kernel(const float* __restrict__ x, const float* __restrict__ W,
                  const float* __restrict__ b, float* __restrict__ h) {
    __shared__ float Ws[40 * 128];
    __shared__ float xs[32 * 40];
    __shared__ float bs[128];
    int tid = threadIdx.x;
    int n0 = blockIdx.x * 32;
    for (int i = tid; i < 40 * 128; i += 256) Ws[i] = W[i];
    if (tid < 128) bs[tid] = b[tid];
    for (int i = tid; i < 32 * 40; i += 256) {
        int n = n0 + (i / 40);
        xs[i] = (n < N_NODES) ? x[(size_t)n * 40 + (i % 40)] : 0.f;
    }
    __syncthreads();
    for (int i = tid; i < 32 * 128; i += 256) {
        int nl = i >> 7, col = i & 127;
        int n = n0 + nl;
        if (n >= N_NODES) continue;
        float acc = bs[col];
#pragma unroll
        for (int k = 0; k < 40; k++) acc = fmaf(xs[nl * 40 + k], Ws[k * 128 + col], acc);
        h[(size_t)n * 128 + col] = acc;
    }
}

// ---------------- agg[dst] += h[src] over edges (float4 REDG) --------
__global__ void scatter_kernel(const int* __restrict__ ei,
                               const float* __restrict__ h,
                               float* __restrict__ z,
                               int shift, int mask, int ntot) {
    int i = blockIdx.x * blockDim.x + threadIdx.x;
    if (i >= ntot) return;
    int e = i >> shift;
    int c = i & mask;
    int s = ei[e];
    int d = ei[N_EDGES + e];
    int D = (mask + 1) << 2;
    float4 v = *(const float4*)(h + (size_t)s * D + (size_t)c * 4);
    atomicAdd((float4*)(z + (size_t)d * D + (size_t)c * 4), v);
}

// ---------------- HMMA bf16x3 GEMM ----------------
// AMODE 0: A = (1+eps[l])*Af + Agg (fp32 LDG, inline hi/lo split)
// AMODE 1: A = (Ahi, Alo) bf16 pair, [M,K] row-major, loaded via cp.async
// OMODE 0: C fp32 (+bias, optional relu)
// OMODE 1: Chi/Clo bf16 pair (+bias, optional relu)
// BM=128, BN=256, BK=32, 512 threads, 4x4 warps, warp tile 32x64.
#define STG_A_HI 0
#define STG_A_LO 10240
#define STG_B_HI 20480
#define STG_B_LO 40960
#define STG_SIZE 61440
#define GEMM_SMEM (2 * STG_SIZE)

template <int AMODE, int OMODE>
__global__ __launch_bounds__(512, 1)
void mma_gemm(const float* __restrict__ Af, const float* __restrict__ Agg,
              const float* __restrict__ epsp, int l,
              const __nv_bfloat16* __restrict__ Ahi, const __nv_bfloat16* __restrict__ Alo,
              const __nv_bfloat16* __restrict__ Bhi, const __nv_bfloat16* __restrict__ Blo,
              const float* __restrict__ bias,
              float* __restrict__ C, __nv_bfloat16* __restrict__ Chi,
              __nv_bfloat16* __restrict__ Clo,
              int M, int K, int N, int relu) {
    extern __shared__ char smem[];
    const int tid = threadIdx.x;
    const int lane = tid & 31;
    const int w = tid >> 5;
    const int wm = w & 3, wn = w >> 2;
    const int bm = blockIdx.y * 128;
    const int bn = blockIdx.x * 256;
    const uint32_t sbase = smem_u32(smem);

    float sc = 1.f;
    if (AMODE == 0) sc = 1.f + epsp[l];

    // A loader mapping: thread -> (row, 8-elem group)
    const int arow = tid >> 2;
    const int ag = tid & 3;
    const int agrow = bm + arow;
    const uint32_t a_soff = (uint32_t)(arow * 80 + ag * 16);
    const float4* Ap = nullptr;
    const float4* Gp = nullptr;
    if (AMODE == 0 && agrow < M) {
        Ap = (const float4*)(Af + (size_t)agrow * K + ag * 8);
        Gp = (const float4*)(Agg + (size_t)agrow * K + ag * 8);
    }

    float acc[2][8][4];
#pragma unroll
    for (int i = 0; i < 2; i++)
#pragma unroll
        for (int j = 0; j < 8; j++)
#pragma unroll
            for (int q = 0; q < 4; q++) acc[i][j][q] = 0.f;

    const int S = K >> 5;
    float4 ar[2] = {make_float4(0,0,0,0), make_float4(0,0,0,0)};
    float4 gr[2] = {make_float4(0,0,0,0), make_float4(0,0,0,0)};

#define CP_STAGE(st, k0)                                                      \
    {                                                                         \
        uint32_t sb_ = sbase + (st) * STG_SIZE;                               \
        _Pragma("unroll")                                                     \
        for (int j_ = 0; j_ < 2; j_++) {                                      \
            int idx_ = tid + j_ * 512;                                        \
            int n_ = idx_ >> 2, g_ = idx_ & 3;                                \
            size_t go_ = (size_t)(bn + n_) * K + (k0) + g_ * 8;               \
            uint32_t so_ = (uint32_t)(n_ * 80 + g_ * 16);                     \
            CP16(sb_ + STG_B_HI + so_, Bhi + go_);                            \
            CP16(sb_ + STG_B_LO + so_, Blo + go_);                            \
        }                                                                     \
        if (AMODE == 1) {                                                     \
            size_t ago_ = (size_t)agrow * K + (k0) + ag * 8;                  \
            CP16(sb_ + STG_A_HI + a_soff, Ahi + ago_);                        \
            CP16(sb_ + STG_A_LO + a_soff, Alo + ago_);                        \
        }                                                                     \
        asm volatile("cp.async.commit_group;" ::: "memory");                  \
    }

#define LD_A(k0)                                                              \
    if (AMODE == 0 && Ap) {                                                   \
        ar[0] = Ap[(k0) >> 2];                                                \
        ar[1] = Ap[((k0) >> 2) + 1];                                          \
        gr[0] = Gp[(k0) >> 2];                                                \
        gr[1] = Gp[((k0) >> 2) + 1];                                          \
    }

#define ST_A(st)                                                              \
    if (AMODE == 0) {                                                         \
        float v_[8];                                                          \
        v_[0] = fmaf(ar[0].x, sc, gr[0].x); v_[1] = fmaf(ar[0].y, sc, gr[0].y); \
        v_[2] = fmaf(ar[0].z, sc, gr[0].z); v_[3] = fmaf(ar[0].w, sc, gr[0].w); \
        v_[4] = fmaf(ar[1].x, sc, gr[1].x); v_[5] = fmaf(ar[1].y, sc, gr[1].y); \
        v_[6] = fmaf(ar[1].z, sc, gr[1].z); v_[7] = fmaf(ar[1].w, sc, gr[1].w); \
        uint32_t hw_[4], lw_[4];                                              \
        _Pragma("unroll")                                                     \
        for (int j_ = 0; j_ < 4; j_++) {                                      \
            __nv_bfloat162 hp_ = __floats2bfloat162_rn(v_[2*j_], v_[2*j_+1]); \
            float2 hf_ = __bfloat1622float2(hp_);                             \
            __nv_bfloat162 lp_ = __floats2bfloat162_rn(v_[2*j_] - hf_.x,      \
                                                       v_[2*j_+1] - hf_.y);   \
            hw_[j_] = *reinterpret_cast<uint32_t*>(&hp_);                     \
            lw_[j_] = *reinterpret_cast<uint32_t*>(&lp_);                     \
        }                                                                     \
        *(uint4*)(smem + (st) * STG_SIZE + STG_A_HI + a_soff) =               \
            make_uint4(hw_[0], hw_[1], hw_[2], hw_[3]);                       \
        *(uint4*)(smem + (st) * STG_SIZE + STG_A_LO + a_soff) =               \
            make_uint4(lw_[0], lw_[1], lw_[2], lw_[3]);                       \
    }

    // ---- prologue ----
    CP_STAGE(0, 0);
    LD_A(0);
    ST_A(0);
    asm volatile("cp.async.wait_group 0;" ::: "memory");
    __syncthreads();

    const uint32_t a_ld_row = (uint32_t)((wm * 32 + (lane & 15)) * 80);
    const uint32_t a_ld_col = (uint32_t)(((lane >> 4) & 1) * 16);
    const uint32_t b_ld_n = (uint32_t)((wn * 64 + ((lane >> 4) & 1) * 8 + (lane & 7)) * 80);
    const uint32_t b_ld_k = (uint32_t)(((lane >> 3) & 1) * 16);

    for (int s = 0; s < S; s++) {
        const int cst = s & 1;
        const int nst = cst ^ 1;
        if (s + 1 < S) {
            CP_STAGE(nst, (s + 1) << 5);
            LD_A((s + 1) << 5);
        }
        const uint32_t sg = sbase + cst * STG_SIZE;
#pragma unroll
        for (int kh = 0; kh < 2; kh++) {
            uint32_t ahi[2][4], alo[2][4];
#pragma unroll
            for (int mt = 0; mt < 2; mt++) {
                uint32_t ad = sg + a_ld_row + (uint32_t)(mt * 16 * 80) +
                              (uint32_t)(kh * 32) + a_ld_col;
                LDM4(ahi[mt], ad + STG_A_HI);
                LDM4(alo[mt], ad + STG_A_LO);
            }
#pragma unroll
            for (int np = 0; np < 4; np++) {
                uint32_t bd = sg + b_ld_n + (uint32_t)(np * 16 * 80) +
                              (uint32_t)(kh * 32) + b_ld_k;
                uint32_t bh[4], bl[4];
                LDM4(bh, bd + STG_B_HI);
                LDM4(bl, bd + STG_B_LO);
#pragma unroll
                for (int mt = 0; mt < 2; mt++) {
                    MMA16816(acc[mt][np * 2], ahi[mt], bh[0], bh[1]);
                    MMA16816(acc[mt][np * 2], ahi[mt], bl[0], bl[1]);
                    MMA16816(acc[mt][np * 2], alo[mt], bh[0], bh[1]);
                    MMA16816(acc[mt][np * 2 + 1], ahi[mt], bh[2], bh[3]);
                    MMA16816(acc[mt][np * 2 + 1], ahi[mt], bl[2], bl[3]);
                    MMA16816(acc[mt][np * 2 + 1], alo[mt], bh[2], bh[3]);
                }
            }
        }
        if (s + 1 < S) {
            asm volatile("cp.async.wait_group 0;" ::: "memory");
            ST_A(nst);
            __syncthreads();
        }
    }

    // ---- epilogue ----
#pragma unroll
    for (int mt = 0; mt < 2; mt++) {
        int r0 = bm + wm * 32 + mt * 16 + (lane >> 2);
#pragma unroll
        for (int nt = 0; nt < 8; nt++) {
            int col = bn + wn * 64 + nt * 8 + (lane & 3) * 2;
            float b0 = bias[col], b1 = bias[col + 1];
            float v0 = acc[mt][nt][0] + b0, v1 = acc[mt][nt][1] + b1;
            float v2 = acc[mt][nt][2] + b0, v3 = acc[mt][nt][3] + b1;
            if (relu) {
                v0 = fmaxf(v0, 0.f); v1 = fmaxf(v1, 0.f);
                v2 = fmaxf(v2, 0.f); v3 = fmaxf(v3, 0.f);
            }
            if (OMODE == 0) {
                if (r0 < M) *(float2*)(C + (size_t)r0 * N + col) = make_float2(v0, v1);
                if (r0 + 8 < M) *(float2*)(C + (size_t)(r0 + 8) * N + col) = make_float2(v2, v3);
            } else {
                __nv_bfloat162 h01 = __floats2bfloat162_rn(v0, v1);
                __nv_bfloat162 h23 = __floats2bfloat162_rn(v2, v3);
                float2 f01 = __bfloat1622float2(h01);
                float2 f23 = __bfloat1622float2(h23);
                __nv_bfloat162 l01 = __floats2bfloat162_rn(v0 - f01.x, v1 - f01.y);
                __nv_bfloat162 l23 = __floats2bfloat162_rn(v2 - f23.x, v3 - f23.y);
                if (r0 < M) {
                    *(uint32_t*)(Chi + (size_t)r0 * N + col) = *reinterpret_cast<uint32_t*>(&h01);
                    *(uint32_t*)(Clo + (size_t)r0 * N + col) = *reinterpret_cast<uint32_t*>(&l01);
                }
                if (r0 + 8 < M) {
                    *(uint32_t*)(Chi + (size_t)(r0 + 8) * N + col) = *reinterpret_cast<uint32_t*>(&h23);
                    *(uint32_t*)(Clo + (size_t)(r0 + 8) * N + col) = *reinterpret_cast<uint32_t*>(&l23);
                }
            }
        }
    }
#undef CP_STAGE
#undef LD_A
#undef ST_A
}

// ---------------- fused pool + task head (batch is sorted) ----------------
__device__ __forceinline__ int lowb(const int* __restrict__ a, int n, int v) {
    int lo = 0, hi = n;
    while (lo < hi) {
        int m = (lo + hi) >> 1;
        if (a[m] < v) lo = m + 1; else hi = m;
    }
    return lo;
}

__global__ __launch_bounds__(128)
void pool_task_kernel(const int* __restrict__ batch, const float* __restrict__ h,
                      const float* __restrict__ W, const float* __restrict__ b,
                      float* __restrict__ out) {
    int g = blockIdx.x;
    int t = threadIdx.x;  // 128
    int start = lowb(batch, N_NODES, g);
    int end = lowb(batch, N_NODES, g + 1);
    float4 acc = make_float4(0.f, 0.f, 0.f, 0.f);
    for (int n = start; n < end; n++) {
        float4 v = ((const float4*)(h + (size_t)n * 512))[t];
        acc.x += v.x; acc.y += v.y; acc.z += v.z; acc.w += v.w;
    }
    float4 wv = ((const float4*)W)[t];
    float d = acc.x * wv.x + acc.y * wv.y + acc.z * wv.z + acc.w * wv.w;
#pragma unroll
    for (int o = 16; o > 0; o >>= 1) d += __shfl_xor_sync(0xffffffffu, d, o);
    __shared__ float s[4];
    if ((t & 31) == 0) s[t >> 5] = d;
    __syncthreads();
    if (t == 0) out[g] = s[0] + s[1] + s[2] + s[3] + b[0];
}

// ---------------- launch ----------------
extern "C" void kernel_launch(void* const* d_in, const int* in_sizes, int n_in,
                              void* d_out, int out_size) {
    const float* x       = (const float*)d_in[0];
    const int*   ei      = (const int*)d_in[1];
    const int*   batch   = (const int*)d_in[2];
    const float* W_embed = (const float*)d_in[3];
    const float* b_embed = (const float*)d_in[4];
    const float* eps     = (const float*)d_in[5];
    const float* W1[3] = {(const float*)d_in[6],  (const float*)d_in[10], (const float*)d_in[14]};
    const float* b1[3] = {(const float*)d_in[7],  (const float*)d_in[11], (const float*)d_in[15]};
    const float* W2[3] = {(const float*)d_in[8],  (const float*)d_in[12], (const float*)d_in[16]};
    const float* b2[3] = {(const float*)d_in[9],  (const float*)d_in[13], (const float*)d_in[17]};
    const float* W_task = (const float*)d_in[18];
    const float* b_task = (const float*)d_in[19];
    float* out = (float*)d_out;

    float *h, *z;
    __nv_bfloat16 *thi, *tlo, *whi, *wlo;
    cudaGetSymbolAddress((void**)&h, g_h);
    cudaGetSymbolAddress((void**)&z, g_z);
    cudaGetSymbolAddress((void**)&thi, g_thi);
    cudaGetSymbolAddress((void**)&tlo, g_tlo);
    cudaGetSymbolAddress((void**)&whi, g_whi);
    cudaGetSymbolAddress((void**)&wlo, g_wlo);

    cudaFuncSetAttribute(mma_gemm<0, 1>, cudaFuncAttributeMaxDynamicSharedMemorySize, GEMM_SMEM);
    cudaFuncSetAttribute(mma_gemm<1, 0>, cudaFuncAttributeMaxDynamicSharedMemorySize, GEMM_SMEM);

    const size_t woff[6] = {0, 32768, 98304, 163840, 229376, 360448};
    const float* Wsrc[6] = {W1[0], W2[0], W1[1], W2[1], W1[2], W2[2]};
    const int Wk[6] = {128, 256, 256, 256, 256, 512};
    const int Wn[6] = {256, 256, 256, 256, 512, 512};
    for (int i = 0; i < 6; i++) {
        int tot = Wk[i] * Wn[i];
        prep_w<<<(tot + 255) / 256, 256>>>(Wsrc[i], whi + woff[i], wlo + woff[i],
                                           Wk[i], Wn[i]);
    }

    embed_kernel<<<(N_NODES + 31) / 32, 256>>>(x, W_embed, b_embed, h);

    const int Din[3]  = {128, 256, 256};
    const int Dmid[3] = {256, 256, 512};
    const int Dout[3] = {256, 256, 512};
    const int MT = M_PAD / 128;   // 782

    for (int l = 0; l < 3; l++) {
        int D = Din[l];
        cudaMemsetAsync(z, 0, (size_t)N_NODES * D * sizeof(float));

        int shift = (D == 128) ? 5 : 6;
        int mask = (1 << shift) - 1;
        int ntot = N_EDGES << shift;
        scatter_kernel<<<(ntot + 255) / 256, 256>>>(ei, h, z, shift, mask, ntot);

        // GEMM1: A = (1+eps)*h + agg  -> t (bf16 hi/lo), relu
        mma_gemm<0, 1><<<dim3(Dmid[l] / 256, MT), 512, GEMM_SMEM>>>(
            h, z, eps, l, nullptr, nullptr,
            whi + woff[2 * l], wlo + woff[2 * l], b1[l],
            nullptr, thi, tlo, N_NODES, D, Dmid[l], 1);

        // GEMM2: A = t (bf16 pair, cp.async) -> h fp32, relu unless last
        mma_gemm<1, 0><<<dim3(Dout[l] / 256, MT), 512, GEMM_SMEM>>>(
            nullptr, nullptr, nullptr, 0, thi, tlo,
            whi + woff[2 * l + 1], wlo + woff[2 * l + 1], b2[l],
            h, nullptr, nullptr, N_NODES, Dmid[l], Dout[l], (l < 2) ? 1 : 0);
    }

    pool_task_kernel<<<N_GRAPHS, 128>>>(batch, h, W_task, b_task, out);
}

// round 6
// speedup vs baseline: 1.0609x; 1.0609x over previous
#include <cuda_runtime.h>
#include <cuda_bf16.h>
#include <cstdint>
#include <cstddef>

#define N_NODES 100000
#define N_EDGES 300000
#define N_GRAPHS 2048

// ---------------- scratch (no allocations allowed) ----------------
__device__ __align__(256) float g_h[(size_t)N_NODES * 512];
__device__ __align__(256) float g_z[(size_t)N_NODES * 256];
__device__ __align__(256) float g_t[(size_t)N_NODES * 512];
__device__ __align__(256) __nv_bfloat16 g_whi[622592];
__device__ __align__(256) __nv_bfloat16 g_wlo[622592];

// ---------------- helpers ----------------
__device__ __forceinline__ uint32_t smem_u32(const void* p) {
    uint32_t a;
    asm("{ .reg .u64 t; cvta.to.shared.u64 t, %1; cvt.u32.u64 %0, t; }"
        : "=r"(a) : "l"(p));
    return a;
}

#define LDM4(r, addr)                                                         \
    asm volatile("ldmatrix.sync.aligned.m8n8.x4.shared.b16 {%0,%1,%2,%3}, [%4];" \
                 : "=r"((r)[0]), "=r"((r)[1]), "=r"((r)[2]), "=r"((r)[3])     \
                 : "r"(addr))

#define MMA16816(c, a, b0, b1)                                                \
    asm volatile("mma.sync.aligned.m16n8k16.row.col.f32.bf16.bf16.f32 "        \
                 "{%0,%1,%2,%3}, {%4,%5,%6,%7}, {%8,%9}, {%0,%1,%2,%3};"       \
                 : "+f"((c)[0]), "+f"((c)[1]), "+f"((c)[2]), "+f"((c)[3])      \
                 : "r"((a)[0]), "r"((a)[1]), "r"((a)[2]), "r"((a)[3]),         \
                   "r"(b0), "r"(b1))

#define CP16(saddr, gaddr)                                                    \
    asm volatile("cp.async.cg.shared.global [%0], [%1], 16;" ::               \
                 "r"(saddr), "l"(gaddr))

// ---------------- fused weight prep: all 6 matrices in one launch ----------------
// fp32 [K][N] -> bf16 hi/lo [N][K]; element offsets == woff (K*N per matrix)
__global__ __launch_bounds__(256)
void prep_all(const float* __restrict__ w0, const float* __restrict__ w1,
              const float* __restrict__ w2, const float* __restrict__ w3,
              const float* __restrict__ w4, const float* __restrict__ w5,
              __nv_bfloat16* __restrict__ hi, __nv_bfloat16* __restrict__ lo) {
    int i = blockIdx.x * blockDim.x + threadIdx.x;
    if (i >= 622592) return;
    const float* W;
    int off, K, N;
    if (i < 32768)       { W = w0; off = 0;      K = 128; N = 256; }
    else if (i < 98304)  { W = w1; off = 32768;  K = 256; N = 256; }
    else if (i < 163840) { W = w2; off = 98304;  K = 256; N = 256; }
    else if (i < 229376) { W = w3; off = 163840; K = 256; N = 256; }
    else if (i < 360448) { W = w4; off = 229376; K = 256; N = 512; }
    else                 { W = w5; off = 360448; K = 512; N = 512; }
    int j = i - off;
    int k = j / N, n = j % N;
    float x = W[j];
    __nv_bfloat16 h = __float2bfloat16(x);
    float r = x - __bfloat162float(h);
    hi[(size_t)off + (size_t)n * K + k] = h;
    lo[(size_t)off + (size_t)n * K + k] = __float2bfloat16(r);
}

// ---------------- node feature embed: h = x @ W_embed + b ----------------
__global__ __launch_bounds__(256)
void embed_kernel(const float* __restrict__ x, const float* __restrict__ W,
                  const float* __restrict__ b, float* __restrict__ h) {
    __shared__ float Ws[40 * 128];
    __shared__ float xs[32 * 40];
    __shared__ float bs[128];
    int tid = threadIdx.x;
    int n0 = blockIdx.x * 32;
    for (int i = tid; i < 40 * 128; i += 256) Ws[i] = W[i];
    if (tid < 128) bs[tid] = b[tid];
    for (int i = tid; i < 32 * 40; i += 256) {
        int n = n0 + (i / 40);
        xs[i] = (n < N_NODES) ? x[(size_t)n * 40 + (i % 40)] : 0.f;
    }
    __syncthreads();
    for (int i = tid; i < 32 * 128; i += 256) {
        int nl = i >> 7, col = i & 127;
        int n = n0 + nl;
        if (n >= N_NODES) continue;
        float acc = bs[col];
#pragma unroll
        for (int k = 0; k < 40; k++) acc = fmaf(xs[nl * 40 + k], Ws[k * 128 + col], acc);
        h[(size_t)n * 128 + col] = acc;
    }
}

// ---------------- z = (1+eps)*h ----------------
__global__ void scale_kernel(const float4* __restrict__ h, float4* __restrict__ z,
                             const float* __restrict__ eps, int l, int n4) {
    int i = blockIdx.x * blockDim.x + threadIdx.x;
    if (i >= n4) return;
    float s = 1.0f + eps[l];
    float4 v = h[i];
    v.x *= s; v.y *= s; v.z *= s; v.w *= s;
    z[i] = v;
}

// ---------------- z[dst] += h[src] over edges (float4 REDG) --------
__global__ void scatter_kernel(const int* __restrict__ ei,
                               const float* __restrict__ h,
                               float* __restrict__ z,
                               int shift, int mask, int ntot) {
    int i = blockIdx.x * blockDim.x + threadIdx.x;
    if (i >= ntot) return;
    int e = i >> shift;
    int c = i & mask;
    int s = ei[e];
    int d = ei[N_EDGES + e];
    int D = (mask + 1) << 2;
    float4 v = *(const float4*)(h + (size_t)s * D + (size_t)c * 4);
    atomicAdd((float4*)(z + (size_t)d * D + (size_t)c * 4), v);
}

// ---------------- HMMA bf16x3 GEMM: C = act(A[M,K]@W[K,N]+bias) ----------------
// A fp32 row-major, converted in-kernel to bf16 hi/lo.
// BM=128, BN=256, BK=32, 512 threads, 4x4 warps, warp tile 32x64.
#define STG_A_HI 0
#define STG_A_LO 10240
#define STG_B_HI 20480
#define STG_B_LO 40960
#define STG_SIZE 61440
#define GEMM_SMEM (2 * STG_SIZE)

__global__ __launch_bounds__(512, 1)
void mma_gemm(const float* __restrict__ A, const __nv_bfloat16* __restrict__ Bhi,
              const __nv_bfloat16* __restrict__ Blo, const float* __restrict__ bias,
              float* __restrict__ C, int M, int K, int N, int relu) {
    extern __shared__ char smem[];
    const int tid = threadIdx.x;
    const int lane = tid & 31;
    const int w = tid >> 5;
    const int wm = w & 3, wn = w >> 2;
    const int bm = blockIdx.y * 128;
    const int bn = blockIdx.x * 256;
    const uint32_t sbase = smem_u32(smem);

    const int arow = tid >> 2;
    const int ag = tid & 3;
    const int agrow = bm + arow;
    const float4* Ap = (agrow < M)
        ? (const float4*)(A + (size_t)agrow * K + ag * 8) : nullptr;
    const uint32_t a_soff = (uint32_t)(arow * 80 + ag * 16);

    float acc[2][8][4];
#pragma unroll
    for (int i = 0; i < 2; i++)
#pragma unroll
        for (int j = 0; j < 8; j++)
#pragma unroll
            for (int q = 0; q < 4; q++) acc[i][j][q] = 0.f;

    const int S = K >> 5;
    float4 ar[2] = {make_float4(0,0,0,0), make_float4(0,0,0,0)};

#define CP_B(st, k0)                                                          \
    {                                                                         \
        uint32_t sb_ = sbase + (st) * STG_SIZE;                               \
        _Pragma("unroll")                                                     \
        for (int j_ = 0; j_ < 2; j_++) {                                      \
            int idx_ = tid + j_ * 512;                                        \
            int n_ = idx_ >> 2, g_ = idx_ & 3;                                \
            size_t go_ = (size_t)(bn + n_) * K + (k0) + g_ * 8;               \
            uint32_t so_ = (uint32_t)(n_ * 80 + g_ * 16);                     \
            CP16(sb_ + STG_B_HI + so_, Bhi + go_);                            \
            CP16(sb_ + STG_B_LO + so_, Blo + go_);                            \
        }                                                                     \
        asm volatile("cp.async.commit_group;" ::: "memory");                  \
    }

#define LD_A(k0)                                                              \
    if (Ap) {                                                                 \
        ar[0] = Ap[(k0) >> 2];                                                \
        ar[1] = Ap[((k0) >> 2) + 1];                                          \
    }

#define ST_A(st)                                                              \
    {                                                                         \
        float v_[8] = {ar[0].x, ar[0].y, ar[0].z, ar[0].w,                    \
                       ar[1].x, ar[1].y, ar[1].z, ar[1].w};                   \
        uint32_t hw_[4], lw_[4];                                              \
        _Pragma("unroll")                                                     \
        for (int j_ = 0; j_ < 4; j_++) {                                      \
            __nv_bfloat162 hp_ = __floats2bfloat162_rn(v_[2*j_], v_[2*j_+1]); \
            float2 hf_ = __bfloat1622float2(hp_);                             \
            __nv_bfloat162 lp_ = __floats2bfloat162_rn(v_[2*j_] - hf_.x,      \
                                                       v_[2*j_+1] - hf_.y);   \
            hw_[j_] = *reinterpret_cast<uint32_t*>(&hp_);                     \
            lw_[j_] = *reinterpret_cast<uint32_t*>(&lp_);                     \
        }                                                                     \
        *(uint4*)(smem + (st) * STG_SIZE + STG_A_HI + a_soff) =               \
            make_uint4(hw_[0], hw_[1], hw_[2], hw_[3]);                       \
        *(uint4*)(smem + (st) * STG_SIZE + STG_A_LO + a_soff) =               \
            make_uint4(lw_[0], lw_[1], lw_[2], lw_[3]);                       \
    }

    CP_B(0, 0);
    LD_A(0);
    ST_A(0);
    asm volatile("cp.async.wait_group 0;" ::: "memory");
    __syncthreads();

    const uint32_t a_ld_row = (uint32_t)((wm * 32 + (lane & 15)) * 80);
    const uint32_t a_ld_col = (uint32_t)(((lane >> 4) & 1) * 16);
    const uint32_t b_ld_n = (uint32_t)((wn * 64 + ((lane >> 4) & 1) * 8 + (lane & 7)) * 80);
    const uint32_t b_ld_k = (uint32_t)(((lane >> 3) & 1) * 16);

    for (int s = 0; s < S; s++) {
        const int cst = s & 1;
        const int nst = cst ^ 1;
        if (s + 1 < S) {
            CP_B(nst, (s + 1) << 5);
            LD_A((s + 1) << 5);
        }
        const uint32_t sg = sbase + cst * STG_SIZE;
#pragma unroll
        for (int kh = 0; kh < 2; kh++) {
            uint32_t ahi[2][4], alo[2][4];
#pragma unroll
            for (int mt = 0; mt < 2; mt++) {
                uint32_t ad = sg + a_ld_row + (uint32_t)(mt * 16 * 80) +
                              (uint32_t)(kh * 32) + a_ld_col;
                LDM4(ahi[mt], ad + STG_A_HI);
                LDM4(alo[mt], ad + STG_A_LO);
            }
#pragma unroll
            for (int np = 0; np < 4; np++) {
                uint32_t bd = sg + b_ld_n + (uint32_t)(np * 16 * 80) +
                              (uint32_t)(kh * 32) + b_ld_k;
                uint32_t bh[4], bl[4];
                LDM4(bh, bd + STG_B_HI);
                LDM4(bl, bd + STG_B_LO);
#pragma unroll
                for (int mt = 0; mt < 2; mt++) {
                    MMA16816(acc[mt][np * 2], ahi[mt], bh[0], bh[1]);
                    MMA16816(acc[mt][np * 2], ahi[mt], bl[0], bl[1]);
                    MMA16816(acc[mt][np * 2], alo[mt], bh[0], bh[1]);
                    MMA16816(acc[mt][np * 2 + 1], ahi[mt], bh[2], bh[3]);
                    MMA16816(acc[mt][np * 2 + 1], ahi[mt], bl[2], bl[3]);
                    MMA16816(acc[mt][np * 2 + 1], alo[mt], bh[2], bh[3]);
                }
            }
        }
        if (s + 1 < S) {
            asm volatile("cp.async.wait_group 0;" ::: "memory");
            ST_A(nst);
            __syncthreads();
        }
    }

#pragma unroll
    for (int mt = 0; mt < 2; mt++) {
        int r0 = bm + wm * 32 + mt * 16 + (lane >> 2);
#pragma unroll
        for (int nt = 0; nt < 8; nt++) {
            int col = bn + wn * 64 + nt * 8 + (lane & 3) * 2;
            float b0 = bias[col], b1 = bias[col + 1];
            float v0 = acc[mt][nt][0] + b0, v1 = acc[mt][nt][1] + b1;
            float v2 = acc[mt][nt][2] + b0, v3 = acc[mt][nt][3] + b1;
            if (relu) {
                v0 = fmaxf(v0, 0.f); v1 = fmaxf(v1, 0.f);
                v2 = fmaxf(v2, 0.f); v3 = fmaxf(v3, 0.f);
            }
            if (r0 < M) *(float2*)(C + (size_t)r0 * N + col) = make_float2(v0, v1);
            if (r0 + 8 < M) *(float2*)(C + (size_t)(r0 + 8) * N + col) = make_float2(v2, v3);
        }
    }
#undef CP_B
#undef LD_A
#undef ST_A
}

// ---------------- fused pool + task head (batch is sorted) ----------------
__device__ __forceinline__ int lowb(const int* __restrict__ a, int n, int v) {
    int lo = 0, hi = n;
    while (lo < hi) {
        int m = (lo + hi) >> 1;
        if (a[m] < v) lo = m + 1; else hi = m;
    }
    return lo;
}

__global__ __launch_bounds__(128)
void pool_task_kernel(const int* __restrict__ batch, const float* __restrict__ h,
                      const float* __restrict__ W, const float* __restrict__ b,
                      float* __restrict__ out) {
    int g = blockIdx.x;
    int t = threadIdx.x;  // 128
    int start = lowb(batch, N_NODES, g);
    int end = lowb(batch, N_NODES, g + 1);
    float4 acc = make_float4(0.f, 0.f, 0.f, 0.f);
    for (int n = start; n < end; n++) {
        float4 v = ((const float4*)(h + (size_t)n * 512))[t];
        acc.x += v.x; acc.y += v.y; acc.z += v.z; acc.w += v.w;
    }
    float4 wv = ((const float4*)W)[t];
    float d = acc.x * wv.x + acc.y * wv.y + acc.z * wv.z + acc.w * wv.w;
#pragma unroll
    for (int o = 16; o > 0; o >>= 1) d += __shfl_xor_sync(0xffffffffu, d, o);
    __shared__ float s[4];
    if ((t & 31) == 0) s[t >> 5] = d;
    __syncthreads();
    if (t == 0) out[g] = s[0] + s[1] + s[2] + s[3] + b[0];
}

// ---------------- launch ----------------
extern "C" void kernel_launch(void* const* d_in, const int* in_sizes, int n_in,
                              void* d_out, int out_size) {
    const float* x       = (const float*)d_in[0];
    const int*   ei      = (const int*)d_in[1];
    const int*   batch   = (const int*)d_in[2];
    const float* W_embed = (const float*)d_in[3];
    const float* b_embed = (const float*)d_in[4];
    const float* eps     = (const float*)d_in[5];
    const float* W1[3] = {(const float*)d_in[6],  (const float*)d_in[10], (const float*)d_in[14]};
    const float* b1[3] = {(const float*)d_in[7],  (const float*)d_in[11], (const float*)d_in[15]};
    const float* W2[3] = {(const float*)d_in[8],  (const float*)d_in[12], (const float*)d_in[16]};
    const float* b2[3] = {(const float*)d_in[9],  (const float*)d_in[13], (const float*)d_in[17]};
    const float* W_task = (const float*)d_in[18];
    const float* b_task = (const float*)d_in[19];
    float* out = (float*)d_out;

    float *h, *z, *t;
    __nv_bfloat16 *whi, *wlo;
    cudaGetSymbolAddress((void**)&h, g_h);
    cudaGetSymbolAddress((void**)&z, g_z);
    cudaGetSymbolAddress((void**)&t, g_t);
    cudaGetSymbolAddress((void**)&whi, g_whi);
    cudaGetSymbolAddress((void**)&wlo, g_wlo);

    cudaFuncSetAttribute(mma_gemm, cudaFuncAttributeMaxDynamicSharedMemorySize, GEMM_SMEM);

    // launch 0: fused weight prep
    prep_all<<<(622592 + 255) / 256, 256>>>(W1[0], W2[0], W1[1], W2[1], W1[2], W2[2],
                                            whi, wlo);
    // launch 1: embed
    embed_kernel<<<(N_NODES + 31) / 32, 256>>>(x, W_embed, b_embed, h);

    const size_t woff[6] = {0, 32768, 98304, 163840, 229376, 360448};
    const int Din[3]  = {128, 256, 256};
    const int Dmid[3] = {256, 256, 512};
    const int Dout[3] = {256, 256, 512};
    const int MT = (N_NODES + 127) / 128;   // 782

    for (int l = 0; l < 3; l++) {
        int D = Din[l];
        int n4 = N_NODES * D / 4;
        scale_kernel<<<(n4 + 255) / 256, 256>>>((const float4*)h, (float4*)z, eps, l, n4);

        int shift = (D == 128) ? 5 : 6;
        int mask = (1 << shift) - 1;
        int ntot = N_EDGES << shift;
        scatter_kernel<<<(ntot + 255) / 256, 256>>>(ei, h, z, shift, mask, ntot);

        mma_gemm<<<dim3(Dmid[l] / 256, MT), 512, GEMM_SMEM>>>(
            z, whi + woff[2 * l], wlo + woff[2 * l], b1[l], t,
            N_NODES, D, Dmid[l], 1);

        // layer 0: this is launch #5 -> ncu capture target
        mma_gemm<<<dim3(Dout[l] / 256, MT), 512, GEMM_SMEM>>>(
            t, whi + woff[2 * l + 1], wlo + woff[2 * l + 1], b2[l], h,
            N_NODES, Dmid[l], Dout[l], (l < 2) ? 1 : 0);
    }

    pool_task_kernel<<<N_GRAPHS, 128>>>(batch, h, W_task, b_task, out);
}

// round 7
// speedup vs baseline: 1.1061x; 1.0426x over previous
#include <cuda_runtime.h>
#include <cuda_bf16.h>
#include <cstdint>
#include <cstddef>

#define N_NODES 100000
#define N_EDGES 300000
#define N_GRAPHS 2048

// ---------------- scratch (no allocations allowed) ----------------
__device__ __align__(256) float g_h[(size_t)N_NODES * 512];
__device__ __align__(256) float g_z[(size_t)N_NODES * 256];
__device__ __align__(256) float g_t[(size_t)N_NODES * 512];
__device__ __align__(256) __nv_bfloat16 g_whi[622592];
__device__ __align__(256) __nv_bfloat16 g_wlo[622592];

// ---------------- helpers ----------------
__device__ __forceinline__ uint32_t smem_u32(const void* p) {
    uint32_t a;
    asm("{ .reg .u64 t; cvta.to.shared.u64 t, %1; cvt.u32.u64 %0, t; }"
        : "=r"(a) : "l"(p));
    return a;
}

#define LDM4(r, addr)                                                         \
    asm volatile("ldmatrix.sync.aligned.m8n8.x4.shared.b16 {%0,%1,%2,%3}, [%4];" \
                 : "=r"((r)[0]), "=r"((r)[1]), "=r"((r)[2]), "=r"((r)[3])     \
                 : "r"(addr))

#define MMA16816(c, a, b0, b1)                                                \
    asm volatile("mma.sync.aligned.m16n8k16.row.col.f32.bf16.bf16.f32 "        \
                 "{%0,%1,%2,%3}, {%4,%5,%6,%7}, {%8,%9}, {%0,%1,%2,%3};"       \
                 : "+f"((c)[0]), "+f"((c)[1]), "+f"((c)[2]), "+f"((c)[3])      \
                 : "r"((a)[0]), "r"((a)[1]), "r"((a)[2]), "r"((a)[3]),         \
                   "r"(b0), "r"(b1))

#define CP16(saddr, gaddr)                                                    \
    asm volatile("cp.async.cg.shared.global [%0], [%1], 16;" ::               \
                 "r"(saddr), "l"(gaddr))

// ---------------- fused weight prep: all 6 matrices in one launch ----------------
__global__ __launch_bounds__(256)
void prep_all(const float* __restrict__ w0, const float* __restrict__ w1,
              const float* __restrict__ w2, const float* __restrict__ w3,
              const float* __restrict__ w4, const float* __restrict__ w5,
              __nv_bfloat16* __restrict__ hi, __nv_bfloat16* __restrict__ lo) {
    int i = blockIdx.x * blockDim.x + threadIdx.x;
    if (i >= 622592) return;
    const float* W;
    int off, K, N;
    if (i < 32768)       { W = w0; off = 0;      K = 128; N = 256; }
    else if (i < 98304)  { W = w1; off = 32768;  K = 256; N = 256; }
    else if (i < 163840) { W = w2; off = 98304;  K = 256; N = 256; }
    else if (i < 229376) { W = w3; off = 163840; K = 256; N = 256; }
    else if (i < 360448) { W = w4; off = 229376; K = 256; N = 512; }
    else                 { W = w5; off = 360448; K = 512; N = 512; }
    int j = i - off;
    int k = j / N, n = j % N;
    float x = W[j];
    __nv_bfloat16 h = __float2bfloat16(x);
    float r = x - __bfloat162float(h);
    hi[(size_t)off + (size_t)n * K + k] = h;
    lo[(size_t)off + (size_t)n * K + k] = __float2bfloat16(r);
}

// ---------------- embed: h = x @ W_embed + b; z = (1+eps0)*h ----------------
__global__ __launch_bounds__(256)
void embed_kernel(const float* __restrict__ x, const float* __restrict__ W,
                  const float* __restrict__ b, const float* __restrict__ eps,
                  float* __restrict__ h, float* __restrict__ z) {
    __shared__ float Ws[40 * 128];
    __shared__ float xs[32 * 40];
    __shared__ float bs[128];
    int tid = threadIdx.x;
    int n0 = blockIdx.x * 32;
    for (int i = tid; i < 40 * 128; i += 256) Ws[i] = W[i];
    if (tid < 128) bs[tid] = b[tid];
    for (int i = tid; i < 32 * 40; i += 256) {
        int n = n0 + (i / 40);
        xs[i] = (n < N_NODES) ? x[(size_t)n * 40 + (i % 40)] : 0.f;
    }
    __syncthreads();
    float s0 = 1.0f + eps[0];
    for (int i = tid; i < 32 * 128; i += 256) {
        int nl = i >> 7, col = i & 127;
        int n = n0 + nl;
        if (n >= N_NODES) continue;
        float acc = bs[col];
#pragma unroll
        for (int k = 0; k < 40; k++) acc = fmaf(xs[nl * 40 + k], Ws[k * 128 + col], acc);
        h[(size_t)n * 128 + col] = acc;
        z[(size_t)n * 128 + col] = s0 * acc;
    }
}

// ---------------- z = (1+eps)*h ----------------
__global__ void scale_kernel(const float4* __restrict__ h, float4* __restrict__ z,
                             const float* __restrict__ eps, int l, int n4) {
    int i = blockIdx.x * blockDim.x + threadIdx.x;
    if (i >= n4) return;
    float s = 1.0f + eps[l];
    float4 v = h[i];
    v.x *= s; v.y *= s; v.z *= s; v.w *= s;
    z[i] = v;
}

// ---------------- z[dst] += h[src] over edges (float4 REDG) --------
__global__ void scatter_kernel(const int* __restrict__ ei,
                               const float* __restrict__ h,
                               float* __restrict__ z,
                               int shift, int mask, int ntot) {
    int i = blockIdx.x * blockDim.x + threadIdx.x;
    if (i >= ntot) return;
    int e = i >> shift;
    int c = i & mask;
    int s = ei[e];
    int d = ei[N_EDGES + e];
    int D = (mask + 1) << 2;
    float4 v = *(const float4*)(h + (size_t)s * D + (size_t)c * 4);
    atomicAdd((float4*)(z + (size_t)d * D + (size_t)c * 4), v);
}

// ---------------- HMMA bf16x3 GEMM: C = act(A[M,K]@W[K,N]+bias) ----------------
// 3-stage cp.async pipeline (wait_group 1), A fp32 -> bf16 hi/lo in-kernel.
// BM=128, BN=256, BK=32, 512 threads, 4x4 warps, warp tile 32x64.
#define STG_A_HI 0
#define STG_A_LO 10240
#define STG_B_HI 20480
#define STG_B_LO 40960
#define STG_SIZE 61440
#define GEMM_SMEM (3 * STG_SIZE)

__global__ __launch_bounds__(512, 1)
void mma_gemm(const float* __restrict__ A, const __nv_bfloat16* __restrict__ Bhi,
              const __nv_bfloat16* __restrict__ Blo, const float* __restrict__ bias,
              float* __restrict__ C, int M, int K, int N, int relu) {
    extern __shared__ char smem[];
    const int tid = threadIdx.x;
    const int lane = tid & 31;
    const int w = tid >> 5;
    const int wm = w & 3, wn = w >> 2;
    const int bm = blockIdx.y * 128;
    const int bn = blockIdx.x * 256;
    const uint32_t sbase = smem_u32(smem);

    const int arow = tid >> 2;
    const int ag = tid & 3;
    const int agrow = bm + arow;
    const float4* Ap = (agrow < M)
        ? (const float4*)(A + (size_t)agrow * K + ag * 8) : nullptr;
    const uint32_t a_soff = (uint32_t)(arow * 80 + ag * 16);

    float acc[2][8][4];
#pragma unroll
    for (int i = 0; i < 2; i++)
#pragma unroll
        for (int j = 0; j < 8; j++)
#pragma unroll
            for (int q = 0; q < 4; q++) acc[i][j][q] = 0.f;

    const int S = K >> 5;   // 4, 8, or 16
    float4 ar[2] = {make_float4(0,0,0,0), make_float4(0,0,0,0)};

#define CP_B(st, k0)                                                          \
    {                                                                         \
        uint32_t sb_ = sbase + (st) * STG_SIZE;                               \
        _Pragma("unroll")                                                     \
        for (int j_ = 0; j_ < 2; j_++) {                                      \
            int idx_ = tid + j_ * 512;                                        \
            int n_ = idx_ >> 2, g_ = idx_ & 3;                                \
            size_t go_ = (size_t)(bn + n_) * K + (k0) + g_ * 8;               \
            uint32_t so_ = (uint32_t)(n_ * 80 + g_ * 16);                     \
            CP16(sb_ + STG_B_HI + so_, Bhi + go_);                            \
            CP16(sb_ + STG_B_LO + so_, Blo + go_);                            \
        }                                                                     \
        asm volatile("cp.async.commit_group;" ::: "memory");                  \
    }

#define LD_A(k0)                                                              \
    if (Ap) {                                                                 \
        ar[0] = Ap[(k0) >> 2];                                                \
        ar[1] = Ap[((k0) >> 2) + 1];                                          \
    }

#define ST_A(st)                                                              \
    {                                                                         \
        float v_[8] = {ar[0].x, ar[0].y, ar[0].z, ar[0].w,                    \
                       ar[1].x, ar[1].y, ar[1].z, ar[1].w};                   \
        uint32_t hw_[4], lw_[4];                                              \
        _Pragma("unroll")                                                     \
        for (int j_ = 0; j_ < 4; j_++) {                                      \
            __nv_bfloat162 hp_ = __floats2bfloat162_rn(v_[2*j_], v_[2*j_+1]); \
            float2 hf_ = __bfloat1622float2(hp_);                             \
            __nv_bfloat162 lp_ = __floats2bfloat162_rn(v_[2*j_] - hf_.x,      \
                                                       v_[2*j_+1] - hf_.y);   \
            hw_[j_] = *reinterpret_cast<uint32_t*>(&hp_);                     \
            lw_[j_] = *reinterpret_cast<uint32_t*>(&lp_);                     \
        }                                                                     \
        *(uint4*)(smem + (st) * STG_SIZE + STG_A_HI + a_soff) =               \
            make_uint4(hw_[0], hw_[1], hw_[2], hw_[3]);                       \
        *(uint4*)(smem + (st) * STG_SIZE + STG_A_LO + a_soff) =               \
            make_uint4(lw_[0], lw_[1], lw_[2], lw_[3]);                       \
    }

    // ---- prologue: stages 0 and 1 in flight ----
    CP_B(0, 0);
    LD_A(0);
    CP_B(1, 32);
    asm volatile("cp.async.wait_group 1;" ::: "memory");   // stage 0 B done
    ST_A(0);
    LD_A(32);
    __syncthreads();   // stage 0 fully ready

    const uint32_t a_ld_row = (uint32_t)((wm * 32 + (lane & 15)) * 80);
    const uint32_t a_ld_col = (uint32_t)(((lane >> 4) & 1) * 16);
    const uint32_t b_ld_n = (uint32_t)((wn * 64 + ((lane >> 4) & 1) * 8 + (lane & 7)) * 80);
    const uint32_t b_ld_k = (uint32_t)(((lane >> 3) & 1) * 16);

    int cst = 0;
    for (int s = 0; s < S; s++) {
        // prefetch stage s+2 (buffer (s+2)%3 was retired by the barrier
        // at the end of iteration s-1)
        if (s + 2 < S) CP_B((s + 2) % 3, (s + 2) << 5);

        // ---- compute stage s ----
        const uint32_t sg = sbase + cst * STG_SIZE;
#pragma unroll
        for (int kh = 0; kh < 2; kh++) {
            uint32_t ahi[2][4], alo[2][4];
#pragma unroll
            for (int mt = 0; mt < 2; mt++) {
                uint32_t ad = sg + a_ld_row + (uint32_t)(mt * 16 * 80) +
                              (uint32_t)(kh * 32) + a_ld_col;
                LDM4(ahi[mt], ad + STG_A_HI);
                LDM4(alo[mt], ad + STG_A_LO);
            }
#pragma unroll
            for (int np = 0; np < 4; np++) {
                uint32_t bd = sg + b_ld_n + (uint32_t)(np * 16 * 80) +
                              (uint32_t)(kh * 32) + b_ld_k;
                uint32_t bh[4], bl[4];
                LDM4(bh, bd + STG_B_HI);
                LDM4(bl, bd + STG_B_LO);
#pragma unroll
                for (int mt = 0; mt < 2; mt++) {
                    MMA16816(acc[mt][np * 2], ahi[mt], bh[0], bh[1]);
                    MMA16816(acc[mt][np * 2], ahi[mt], bl[0], bl[1]);
                    MMA16816(acc[mt][np * 2], alo[mt], bh[0], bh[1]);
                    MMA16816(acc[mt][np * 2 + 1], ahi[mt], bh[2], bh[3]);
                    MMA16816(acc[mt][np * 2 + 1], ahi[mt], bl[2], bl[3]);
                    MMA16816(acc[mt][np * 2 + 1], alo[mt], bh[2], bh[3]);
                }
            }
        }

        if (s + 1 < S) {
            if (s + 2 < S) {
                asm volatile("cp.async.wait_group 1;" ::: "memory");
            } else {
                asm volatile("cp.async.wait_group 0;" ::: "memory");
            }
            int nb = (s + 1) % 3;
            ST_A(nb);
            if (s + 2 < S) LD_A((s + 2) << 5);
            __syncthreads();   // stage s+1 ready; retires stage s buffer
            cst = nb;
        }
    }

    // ---- epilogue: bias + relu, direct stores ----
#pragma unroll
    for (int mt = 0; mt < 2; mt++) {
        int r0 = bm + wm * 32 + mt * 16 + (lane >> 2);
#pragma unroll
        for (int nt = 0; nt < 8; nt++) {
            int col = bn + wn * 64 + nt * 8 + (lane & 3) * 2;
            float b0 = bias[col], b1 = bias[col + 1];
            float v0 = acc[mt][nt][0] + b0, v1 = acc[mt][nt][1] + b1;
            float v2 = acc[mt][nt][2] + b0, v3 = acc[mt][nt][3] + b1;
            if (relu) {
                v0 = fmaxf(v0, 0.f); v1 = fmaxf(v1, 0.f);
                v2 = fmaxf(v2, 0.f); v3 = fmaxf(v3, 0.f);
            }
            if (r0 < M) *(float2*)(C + (size_t)r0 * N + col) = make_float2(v0, v1);
            if (r0 + 8 < M) *(float2*)(C + (size_t)(r0 + 8) * N + col) = make_float2(v2, v3);
        }
    }
#undef CP_B
#undef LD_A
#undef ST_A
}

// ---------------- fused pool + task head (batch is sorted) ----------------
__device__ __forceinline__ int lowb(const int* __restrict__ a, int n, int v) {
    int lo = 0, hi = n;
    while (lo < hi) {
        int m = (lo + hi) >> 1;
        if (a[m] < v) lo = m + 1; else hi = m;
    }
    return lo;
}

__global__ __launch_bounds__(128)
void pool_task_kernel(const int* __restrict__ batch, const float* __restrict__ h,
                      const float* __restrict__ W, const float* __restrict__ b,
                      float* __restrict__ out) {
    int g = blockIdx.x;
    int t = threadIdx.x;  // 128
    int start = lowb(batch, N_NODES, g);
    int end = lowb(batch, N_NODES, g + 1);
    float4 acc = make_float4(0.f, 0.f, 0.f, 0.f);
    for (int n = start; n < end; n++) {
        float4 v = ((const float4*)(h + (size_t)n * 512))[t];
        acc.x += v.x; acc.y += v.y; acc.z += v.z; acc.w += v.w;
    }
    float4 wv = ((const float4*)W)[t];
    float d = acc.x * wv.x + acc.y * wv.y + acc.z * wv.z + acc.w * wv.w;
#pragma unroll
    for (int o = 16; o > 0; o >>= 1) d += __shfl_xor_sync(0xffffffffu, d, o);
    __shared__ float s[4];
    if ((t & 31) == 0) s[t >> 5] = d;
    __syncthreads();
    if (t == 0) out[g] = s[0] + s[1] + s[2] + s[3] + b[0];
}

// ---------------- launch ----------------
extern "C" void kernel_launch(void* const* d_in, const int* in_sizes, int n_in,
                              void* d_out, int out_size) {
    const float* x       = (const float*)d_in[0];
    const int*   ei      = (const int*)d_in[1];
    const int*   batch   = (const int*)d_in[2];
    const float* W_embed = (const float*)d_in[3];
    const float* b_embed = (const float*)d_in[4];
    const float* eps     = (const float*)d_in[5];
    const float* W1[3] = {(const float*)d_in[6],  (const float*)d_in[10], (const float*)d_in[14]};
    const float* b1[3] = {(const float*)d_in[7],  (const float*)d_in[11], (const float*)d_in[15]};
    const float* W2[3] = {(const float*)d_in[8],  (const float*)d_in[12], (const float*)d_in[16]};
    const float* b2[3] = {(const float*)d_in[9],  (const float*)d_in[13], (const float*)d_in[17]};
    const float* W_task = (const float*)d_in[18];
    const float* b_task = (const float*)d_in[19];
    float* out = (float*)d_out;

    float *h, *z, *t;
    __nv_bfloat16 *whi, *wlo;
    cudaGetSymbolAddress((void**)&h, g_h);
    cudaGetSymbolAddress((void**)&z, g_z);
    cudaGetSymbolAddress((void**)&t, g_t);
    cudaGetSymbolAddress((void**)&whi, g_whi);
    cudaGetSymbolAddress((void**)&wlo, g_wlo);

    cudaFuncSetAttribute(mma_gemm, cudaFuncAttributeMaxDynamicSharedMemorySize, GEMM_SMEM);

    prep_all<<<(622592 + 255) / 256, 256>>>(W1[0], W2[0], W1[1], W2[1], W1[2], W2[2],
                                            whi, wlo);
    embed_kernel<<<(N_NODES + 31) / 32, 256>>>(x, W_embed, b_embed, eps, h, z);

    const size_t woff[6] = {0, 32768, 98304, 163840, 229376, 360448};
    const int Din[3]  = {128, 256, 256};
    const int Dmid[3] = {256, 256, 512};
    const int Dout[3] = {256, 256, 512};
    const int MT = (N_NODES + 127) / 128;   // 782

    for (int l = 0; l < 3; l++) {
        int D = Din[l];
        if (l > 0) {
            int n4 = N_NODES * D / 4;
            scale_kernel<<<(n4 + 255) / 256, 256>>>((const float4*)h, (float4*)z,
                                                    eps, l, n4);
        }

        int shift = (D == 128) ? 5 : 6;
        int mask = (1 << shift) - 1;
        int ntot = N_EDGES << shift;
        scatter_kernel<<<(ntot + 255) / 256, 256>>>(ei, h, z, shift, mask, ntot);

        mma_gemm<<<dim3(Dmid[l] / 256, MT), 512, GEMM_SMEM>>>(
            z, whi + woff[2 * l], wlo + woff[2 * l], b1[l], t,
            N_NODES, D, Dmid[l], 1);

        mma_gemm<<<dim3(Dout[l] / 256, MT), 512, GEMM_SMEM>>>(
            t, whi + woff[2 * l + 1], wlo + woff[2 * l + 1], b2[l], h,
            N_NODES, Dmid[l], Dout[l], (l < 2) ? 1 : 0);
    }

    pool_task_kernel<<<N_GRAPHS, 128>>>(batch, h, W_task, b_task, out);
}

// round 8
// speedup vs baseline: 1.1945x; 1.0799x over previous
#include <cuda_runtime.h>
#include <cuda_bf16.h>
#include <cstdint>
#include <cstddef>

#define N_NODES 100000
#define N_EDGES 300000
#define N_GRAPHS 2048

// ---------------- scratch (no allocations allowed) ----------------
__device__ __align__(256) float g_h[(size_t)N_NODES * 512];
__device__ __align__(256) float g_z[(size_t)N_NODES * 256];
__device__ __align__(256) float g_t[(size_t)N_NODES * 512];
__device__ __align__(256) __nv_bfloat16 g_whi[622592];
__device__ __align__(256) __nv_bfloat16 g_wlo[622592];

// ---------------- helpers ----------------
__device__ __forceinline__ uint32_t smem_u32(const void* p) {
    uint32_t a;
    asm("{ .reg .u64 t; cvta.to.shared.u64 t, %1; cvt.u32.u64 %0, t; }"
        : "=r"(a) : "l"(p));
    return a;
}

#define LDM4(r, addr)                                                         \
    asm volatile("ldmatrix.sync.aligned.m8n8.x4.shared.b16 {%0,%1,%2,%3}, [%4];" \
                 : "=r"((r)[0]), "=r"((r)[1]), "=r"((r)[2]), "=r"((r)[3])     \
                 : "r"(addr))

#define MMA16816(c, a, b0, b1)                                                \
    asm volatile("mma.sync.aligned.m16n8k16.row.col.f32.bf16.bf16.f32 "        \
                 "{%0,%1,%2,%3}, {%4,%5,%6,%7}, {%8,%9}, {%0,%1,%2,%3};"       \
                 : "+f"((c)[0]), "+f"((c)[1]), "+f"((c)[2]), "+f"((c)[3])      \
                 : "r"((a)[0]), "r"((a)[1]), "r"((a)[2]), "r"((a)[3]),         \
                   "r"(b0), "r"(b1))

#define CP16(saddr, gaddr)                                                    \
    asm volatile("cp.async.cg.shared.global [%0], [%1], 16;" ::               \
                 "r"(saddr), "l"(gaddr))

// 64B-row XOR swizzle: c16 is the 16B column (0..3)
#define SWZ(row, c16) ((uint32_t)((row) * 64 + ((((c16) ^ (((row) >> 1) & 3))) << 4)))

// ---------------- fused weight prep: all 6 matrices in one launch ----------------
__global__ __launch_bounds__(256)
void prep_all(const float* __restrict__ w0, const float* __restrict__ w1,
              const float* __restrict__ w2, const float* __restrict__ w3,
              const float* __restrict__ w4, const float* __restrict__ w5,
              __nv_bfloat16* __restrict__ hi, __nv_bfloat16* __restrict__ lo) {
    int i = blockIdx.x * blockDim.x + threadIdx.x;
    if (i >= 622592) return;
    const float* W;
    int off, K, N;
    if (i < 32768)       { W = w0; off = 0;      K = 128; N = 256; }
    else if (i < 98304)  { W = w1; off = 32768;  K = 256; N = 256; }
    else if (i < 163840) { W = w2; off = 98304;  K = 256; N = 256; }
    else if (i < 229376) { W = w3; off = 163840; K = 256; N = 256; }
    else if (i < 360448) { W = w4; off = 229376; K = 256; N = 512; }
    else                 { W = w5; off = 360448; K = 512; N = 512; }
    int j = i - off;
    int k = j / N, n = j % N;
    float x = W[j];
    __nv_bfloat16 h = __float2bfloat16(x);
    float r = x - __bfloat162float(h);
    hi[(size_t)off + (size_t)n * K + k] = h;
    lo[(size_t)off + (size_t)n * K + k] = __float2bfloat16(r);
}

// ---------------- embed: h = x @ W_embed + b; z = (1+eps0)*h ----------------
__global__ __launch_bounds__(256)
void embed_kernel(const float* __restrict__ x, const float* __restrict__ W,
                  const float* __restrict__ b, const float* __restrict__ eps,
                  float* __restrict__ h, float* __restrict__ z) {
    __shared__ float Ws[40 * 128];
    __shared__ float xs[32 * 40];
    __shared__ float bs[128];
    int tid = threadIdx.x;
    int n0 = blockIdx.x * 32;
    for (int i = tid; i < 40 * 128; i += 256) Ws[i] = W[i];
    if (tid < 128) bs[tid] = b[tid];
    for (int i = tid; i < 32 * 40; i += 256) {
        int n = n0 + (i / 40);
        xs[i] = (n < N_NODES) ? x[(size_t)n * 40 + (i % 40)] : 0.f;
    }
    __syncthreads();
    float s0 = 1.0f + eps[0];
    for (int i = tid; i < 32 * 128; i += 256) {
        int nl = i >> 7, col = i & 127;
        int n = n0 + nl;
        if (n >= N_NODES) continue;
        float acc = bs[col];
#pragma unroll
        for (int k = 0; k < 40; k++) acc = fmaf(xs[nl * 40 + k], Ws[k * 128 + col], acc);
        h[(size_t)n * 128 + col] = acc;
        z[(size_t)n * 128 + col] = s0 * acc;
    }
}

// ---------------- z = (1+eps)*h ----------------
__global__ void scale_kernel(const float4* __restrict__ h, float4* __restrict__ z,
                             const float* __restrict__ eps, int l, int n4) {
    int i = blockIdx.x * blockDim.x + threadIdx.x;
    if (i >= n4) return;
    float s = 1.0f + eps[l];
    float4 v = h[i];
    v.x *= s; v.y *= s; v.z *= s; v.w *= s;
    z[i] = v;
}

// ---------------- z[dst] += h[src] over edges (float4 REDG) --------
__global__ void scatter_kernel(const int* __restrict__ ei,
                               const float* __restrict__ h,
                               float* __restrict__ z,
                               int shift, int mask, int ntot) {
    int i = blockIdx.x * blockDim.x + threadIdx.x;
    if (i >= ntot) return;
    int e = i >> shift;
    int c = i & mask;
    int s = ei[e];
    int d = ei[N_EDGES + e];
    int D = (mask + 1) << 2;
    float4 v = *(const float4*)(h + (size_t)s * D + (size_t)c * 4);
    atomicAdd((float4*)(z + (size_t)d * D + (size_t)c * 4), v);
}

// ---------------- HMMA bf16x3 GEMM: C = act(A[M,K]@W[K,N]+bias) ----------------
// BM=128, BN=128, BK=32, 256 threads, 4x2 warps, warp tile 32x64.
// 3-stage cp.async pipeline, 64B rows + XOR swizzle, 2 CTAs/SM.
#define STG_A_HI 0
#define STG_A_LO 8192
#define STG_B_HI 16384
#define STG_B_LO 24576
#define STG_SIZE 32768
#define GEMM_SMEM (3 * STG_SIZE)

__global__ __launch_bounds__(256, 2)
void mma_gemm(const float* __restrict__ A, const __nv_bfloat16* __restrict__ Bhi,
              const __nv_bfloat16* __restrict__ Blo, const float* __restrict__ bias,
              float* __restrict__ C, int M, int K, int N, int relu) {
    extern __shared__ char smem[];
    const int tid = threadIdx.x;
    const int lane = tid & 31;
    const int w = tid >> 5;          // 0..7
    const int wm = w & 3, wn = w >> 2;  // 4 x 2 warp grid
    const int bm = blockIdx.y * 128;
    const int bn = blockIdx.x * 128;
    const uint32_t sbase = smem_u32(smem);

    // A loader: thread handles rows (tid>>2) and (tid>>2)+64, quarter (tid&3)
    // each segment = 8 consecutive fp32 -> one 16B bf16 chunk (c16 = quarter)
    const int ar0 = tid >> 2;
    const int aq = tid & 3;
    const float4* Ap0 = (bm + ar0 < M)
        ? (const float4*)(A + (size_t)(bm + ar0) * K + aq * 8) : nullptr;
    const float4* Ap1 = (bm + ar0 + 64 < M)
        ? (const float4*)(A + (size_t)(bm + ar0 + 64) * K + aq * 8) : nullptr;
    const uint32_t as0 = SWZ(ar0, aq);
    const uint32_t as1 = SWZ(ar0 + 64, aq);

    float acc[2][8][4];
#pragma unroll
    for (int i = 0; i < 2; i++)
#pragma unroll
        for (int j = 0; j < 8; j++)
#pragma unroll
            for (int q = 0; q < 4; q++) acc[i][j][q] = 0.f;

    const int S = K >> 5;
    float4 ar[2][2];
#pragma unroll
    for (int i = 0; i < 2; i++)
#pragma unroll
        for (int j = 0; j < 2; j++) ar[i][j] = make_float4(0.f, 0.f, 0.f, 0.f);

#define CP_B(st, k0)                                                          \
    {                                                                         \
        uint32_t sb_ = sbase + (st) * STG_SIZE;                               \
        _Pragma("unroll")                                                     \
        for (int j_ = 0; j_ < 2; j_++) {                                      \
            int idx_ = tid + j_ * 256;                                        \
            int n_ = idx_ >> 2, g_ = idx_ & 3;                                \
            size_t go_ = (size_t)(bn + n_) * K + (k0) + g_ * 8;               \
            uint32_t so_ = SWZ(n_, g_);                                       \
            CP16(sb_ + STG_B_HI + so_, Bhi + go_);                            \
            CP16(sb_ + STG_B_LO + so_, Blo + go_);                            \
        }                                                                     \
        asm volatile("cp.async.commit_group;" ::: "memory");                  \
    }

#define LD_A(k0)                                                              \
    {                                                                         \
        if (Ap0) { ar[0][0] = Ap0[(k0) >> 2]; ar[0][1] = Ap0[((k0) >> 2) + 1]; } \
        if (Ap1) { ar[1][0] = Ap1[(k0) >> 2]; ar[1][1] = Ap1[((k0) >> 2) + 1]; } \
    }

#define ST_A(st)                                                              \
    {                                                                         \
        _Pragma("unroll")                                                     \
        for (int sgm_ = 0; sgm_ < 2; sgm_++) {                                \
            float v_[8] = {ar[sgm_][0].x, ar[sgm_][0].y, ar[sgm_][0].z,       \
                           ar[sgm_][0].w, ar[sgm_][1].x, ar[sgm_][1].y,       \
                           ar[sgm_][1].z, ar[sgm_][1].w};                     \
            uint32_t hw_[4], lw_[4];                                          \
            _Pragma("unroll")                                                 \
            for (int j_ = 0; j_ < 4; j_++) {                                  \
                __nv_bfloat162 hp_ = __floats2bfloat162_rn(v_[2*j_], v_[2*j_+1]); \
                float2 hf_ = __bfloat1622float2(hp_);                         \
                __nv_bfloat162 lp_ = __floats2bfloat162_rn(v_[2*j_] - hf_.x,  \
                                                           v_[2*j_+1] - hf_.y); \
                hw_[j_] = *reinterpret_cast<uint32_t*>(&hp_);                 \
                lw_[j_] = *reinterpret_cast<uint32_t*>(&lp_);                 \
            }                                                                 \
            uint32_t off_ = (sgm_ == 0) ? as0 : as1;                          \
            *(uint4*)(smem + (st) * STG_SIZE + STG_A_HI + off_) =             \
                make_uint4(hw_[0], hw_[1], hw_[2], hw_[3]);                   \
            *(uint4*)(smem + (st) * STG_SIZE + STG_A_LO + off_) =             \
                make_uint4(lw_[0], lw_[1], lw_[2], lw_[3]);                   \
        }                                                                     \
    }

    // ---- prologue: stages 0 and 1 in flight ----
    CP_B(0, 0);
    LD_A(0);
    CP_B(1, 32);
    asm volatile("cp.async.wait_group 1;" ::: "memory");
    ST_A(0);
    LD_A(32);
    __syncthreads();

    // per-lane ldmatrix row bases (row*64) and swizzle keys
    uint32_t a_base[2], a_key[2];
#pragma unroll
    for (int mt = 0; mt < 2; mt++) {
        int row = wm * 32 + mt * 16 + (lane & 15);
        a_base[mt] = (uint32_t)(row * 64);
        a_key[mt] = (uint32_t)((row >> 1) & 3);
    }
    const uint32_t a_c16_bit = (lane >> 4) & 1;
    uint32_t b_base[4], b_key[4];
#pragma unroll
    for (int np = 0; np < 4; np++) {
        int row = wn * 64 + np * 16 + ((lane >> 4) & 1) * 8 + (lane & 7);
        b_base[np] = (uint32_t)(row * 64);
        b_key[np] = (uint32_t)((row >> 1) & 3);
    }
    const uint32_t b_c16_bit = (lane >> 3) & 1;

    int cst = 0;
    for (int s = 0; s < S; s++) {
        if (s + 2 < S) CP_B((s + 2) % 3, (s + 2) << 5);

        const uint32_t sg = sbase + cst * STG_SIZE;
#pragma unroll
        for (int kh = 0; kh < 2; kh++) {
            uint32_t ahi[2][4], alo[2][4];
#pragma unroll
            for (int mt = 0; mt < 2; mt++) {
                uint32_t c16 = (uint32_t)(kh * 2) + a_c16_bit;
                uint32_t ad = sg + a_base[mt] + ((c16 ^ a_key[mt]) << 4);
                LDM4(ahi[mt], ad + STG_A_HI);
                LDM4(alo[mt], ad + STG_A_LO);
            }
#pragma unroll
            for (int np = 0; np < 4; np++) {
                uint32_t c16 = (uint32_t)(kh * 2) + b_c16_bit;
                uint32_t bd = sg + b_base[np] + ((c16 ^ b_key[np]) << 4);
                uint32_t bh[4], bl[4];
                LDM4(bh, bd + STG_B_HI);
                LDM4(bl, bd + STG_B_LO);
#pragma unroll
                for (int mt = 0; mt < 2; mt++) {
                    MMA16816(acc[mt][np * 2], ahi[mt], bh[0], bh[1]);
                    MMA16816(acc[mt][np * 2], ahi[mt], bl[0], bl[1]);
                    MMA16816(acc[mt][np * 2], alo[mt], bh[0], bh[1]);
                    MMA16816(acc[mt][np * 2 + 1], ahi[mt], bh[2], bh[3]);
                    MMA16816(acc[mt][np * 2 + 1], ahi[mt], bl[2], bl[3]);
                    MMA16816(acc[mt][np * 2 + 1], alo[mt], bh[2], bh[3]);
                }
            }
        }

        if (s + 1 < S) {
            if (s + 2 < S) {
                asm volatile("cp.async.wait_group 1;" ::: "memory");
            } else {
                asm volatile("cp.async.wait_group 0;" ::: "memory");
            }
            int nb = (s + 1) % 3;
            ST_A(nb);
            if (s + 2 < S) LD_A((s + 2) << 5);
            __syncthreads();
            cst = nb;
        }
    }

    // ---- epilogue: bias + relu, direct stores ----
#pragma unroll
    for (int mt = 0; mt < 2; mt++) {
        int r0 = bm + wm * 32 + mt * 16 + (lane >> 2);
#pragma unroll
        for (int nt = 0; nt < 8; nt++) {
            int col = bn + wn * 64 + nt * 8 + (lane & 3) * 2;
            float b0 = bias[col], b1 = bias[col + 1];
            float v0 = acc[mt][nt][0] + b0, v1 = acc[mt][nt][1] + b1;
            float v2 = acc[mt][nt][2] + b0, v3 = acc[mt][nt][3] + b1;
            if (relu) {
                v0 = fmaxf(v0, 0.f); v1 = fmaxf(v1, 0.f);
                v2 = fmaxf(v2, 0.f); v3 = fmaxf(v3, 0.f);
            }
            if (r0 < M) *(float2*)(C + (size_t)r0 * N + col) = make_float2(v0, v1);
            if (r0 + 8 < M) *(float2*)(C + (size_t)(r0 + 8) * N + col) = make_float2(v2, v3);
        }
    }
#undef CP_B
#undef LD_A
#undef ST_A
}

// ---------------- fused pool + task head (batch is sorted) ----------------
__device__ __forceinline__ int lowb(const int* __restrict__ a, int n, int v) {
    int lo = 0, hi = n;
    while (lo < hi) {
        int m = (lo + hi) >> 1;
        if (a[m] < v) lo = m + 1; else hi = m;
    }
    return lo;
}

__global__ __launch_bounds__(128)
void pool_task_kernel(const int* __restrict__ batch, const float* __restrict__ h,
                      const float* __restrict__ W, const float* __restrict__ b,
                      float* __restrict__ out) {
    int g = blockIdx.x;
    int t = threadIdx.x;  // 128
    int start = lowb(batch, N_NODES, g);
    int end = lowb(batch, N_NODES, g + 1);
    float4 acc = make_float4(0.f, 0.f, 0.f, 0.f);
    for (int n = start; n < end; n++) {
        float4 v = ((const float4*)(h + (size_t)n * 512))[t];
        acc.x += v.x; acc.y += v.y; acc.z += v.z; acc.w += v.w;
    }
    float4 wv = ((const float4*)W)[t];
    float d = acc.x * wv.x + acc.y * wv.y + acc.z * wv.z + acc.w * wv.w;
#pragma unroll
    for (int o = 16; o > 0; o >>= 1) d += __shfl_xor_sync(0xffffffffu, d, o);
    __shared__ float s[4];
    if ((t & 31) == 0) s[t >> 5] = d;
    __syncthreads();
    if (t == 0) out[g] = s[0] + s[1] + s[2] + s[3] + b[0];
}

// ---------------- launch ----------------
extern "C" void kernel_launch(void* const* d_in, const int* in_sizes, int n_in,
                              void* d_out, int out_size) {
    const float* x       = (const float*)d_in[0];
    const int*   ei      = (const int*)d_in[1];
    const int*   batch   = (const int*)d_in[2];
    const float* W_embed = (const float*)d_in[3];
    const float* b_embed = (const float*)d_in[4];
    const float* eps     = (const float*)d_in[5];
    const float* W1[3] = {(const float*)d_in[6],  (const float*)d_in[10], (const float*)d_in[14]};
    const float* b1[3] = {(const float*)d_in[7],  (const float*)d_in[11], (const float*)d_in[15]};
    const float* W2[3] = {(const float*)d_in[8],  (const float*)d_in[12], (const float*)d_in[16]};
    const float* b2[3] = {(const float*)d_in[9],  (const float*)d_in[13], (const float*)d_in[17]};
    const float* W_task = (const float*)d_in[18];
    const float* b_task = (const float*)d_in[19];
    float* out = (float*)d_out;

    float *h, *z, *t;
    __nv_bfloat16 *whi, *wlo;
    cudaGetSymbolAddress((void**)&h, g_h);
    cudaGetSymbolAddress((void**)&z, g_z);
    cudaGetSymbolAddress((void**)&t, g_t);
    cudaGetSymbolAddress((void**)&whi, g_whi);
    cudaGetSymbolAddress((void**)&wlo, g_wlo);

    cudaFuncSetAttribute(mma_gemm, cudaFuncAttributeMaxDynamicSharedMemorySize, GEMM_SMEM);

    prep_all<<<(622592 + 255) / 256, 256>>>(W1[0], W2[0], W1[1], W2[1], W1[2], W2[2],
                                            whi, wlo);
    embed_kernel<<<(N_NODES + 31) / 32, 256>>>(x, W_embed, b_embed, eps, h, z);

    const size_t woff[6] = {0, 32768, 98304, 163840, 229376, 360448};
    const int Din[3]  = {128, 256, 256};
    const int Dmid[3] = {256, 256, 512};
    const int Dout[3] = {256, 256, 512};
    const int MT = (N_NODES + 127) / 128;   // 782

    for (int l = 0; l < 3; l++) {
        int D = Din[l];
        if (l > 0) {
            int n4 = N_NODES * D / 4;
            scale_kernel<<<(n4 + 255) / 256, 256>>>((const float4*)h, (float4*)z,
                                                    eps, l, n4);
        }

        int shift = (D == 128) ? 5 : 6;
        int mask = (1 << shift) - 1;
        int ntot = N_EDGES << shift;
        scatter_kernel<<<(ntot + 255) / 256, 256>>>(ei, h, z, shift, mask, ntot);

        mma_gemm<<<dim3(Dmid[l] / 128, MT), 256, GEMM_SMEM>>>(
            z, whi + woff[2 * l], wlo + woff[2 * l], b1[l], t,
            N_NODES, D, Dmid[l], 1);

        mma_gemm<<<dim3(Dout[l] / 128, MT), 256, GEMM_SMEM>>>(
            t, whi + woff[2 * l + 1], wlo + woff[2 * l + 1], b2[l], h,
            N_NODES, Dmid[l], Dout[l], (l < 2) ? 1 : 0);
    }

    pool_task_kernel<<<N_GRAPHS, 128>>>(batch, h, W_task, b_task, out);
}

// round 9
// speedup vs baseline: 1.2026x; 1.0068x over previous
#include <cuda_runtime.h>
#include <cuda_bf16.h>
#include <cstdint>
#include <cstddef>

#define N_NODES 100000
#define M_PAD   100096
#define N_EDGES 300000
#define N_GRAPHS 2048

// ---------------- scratch (no allocations allowed) ----------------
__device__ __align__(256) float g_h[(size_t)N_NODES * 512];
__device__ __align__(256) float g_z[(size_t)N_NODES * 256];
__device__ __align__(256) uint32_t g_zp[(size_t)M_PAD * 256];   // packed z (hi/lo)
__device__ __align__(256) uint32_t g_tp[(size_t)M_PAD * 512];   // packed t (hi/lo)
__device__ __align__(256) __nv_bfloat16 g_whi[622592];
__device__ __align__(256) __nv_bfloat16 g_wlo[622592];

// packed A layout: element (r, c) of an [M, K] matrix lives at byte offset
//   r*K*4 + (c>>3)*32 + (c&7)*2        (hi)
//   r*K*4 + (c>>3)*32 + 16 + (c&7)*2   (lo)
// i.e. per 8-element group: 16B of hi bf16 then 16B of lo bf16.

// ---------------- helpers ----------------
__device__ __forceinline__ uint32_t smem_u32(const void* p) {
    uint32_t a;
    asm("{ .reg .u64 t; cvta.to.shared.u64 t, %1; cvt.u32.u64 %0, t; }"
        : "=r"(a) : "l"(p));
    return a;
}

#define LDM4(r, addr)                                                         \
    asm volatile("ldmatrix.sync.aligned.m8n8.x4.shared.b16 {%0,%1,%2,%3}, [%4];" \
                 : "=r"((r)[0]), "=r"((r)[1]), "=r"((r)[2]), "=r"((r)[3])     \
                 : "r"(addr))

#define MMA16816(c, a, b0, b1)                                                \
    asm volatile("mma.sync.aligned.m16n8k16.row.col.f32.bf16.bf16.f32 "        \
                 "{%0,%1,%2,%3}, {%4,%5,%6,%7}, {%8,%9}, {%0,%1,%2,%3};"       \
                 : "+f"((c)[0]), "+f"((c)[1]), "+f"((c)[2]), "+f"((c)[3])      \
                 : "r"((a)[0]), "r"((a)[1]), "r"((a)[2]), "r"((a)[3]),         \
                   "r"(b0), "r"(b1))

#define CP16(saddr, gaddr)                                                    \
    asm volatile("cp.async.cg.shared.global [%0], [%1], 16;" ::               \
                 "r"(saddr), "l"(gaddr))

// 64B-row XOR swizzle for B: c16 is the 16B column (0..3)
#define SWZ(row, c16) ((uint32_t)((row) * 64 + ((((c16) ^ (((row) >> 1) & 3))) << 4)))

__device__ __forceinline__ void split2(float a, float b, uint32_t& hw, uint32_t& lw) {
    __nv_bfloat162 hp = __floats2bfloat162_rn(a, b);
    float2 hf = __bfloat1622float2(hp);
    __nv_bfloat162 lp = __floats2bfloat162_rn(a - hf.x, b - hf.y);
    hw = *reinterpret_cast<uint32_t*>(&hp);
    lw = *reinterpret_cast<uint32_t*>(&lp);
}

// ---------------- fused weight prep: all 6 matrices in one launch ----------------
__global__ __launch_bounds__(256)
void prep_all(const float* __restrict__ w0, const float* __restrict__ w1,
              const float* __restrict__ w2, const float* __restrict__ w3,
              const float* __restrict__ w4, const float* __restrict__ w5,
              __nv_bfloat16* __restrict__ hi, __nv_bfloat16* __restrict__ lo) {
    int i = blockIdx.x * blockDim.x + threadIdx.x;
    if (i >= 622592) return;
    const float* W;
    int off, K, N;
    if (i < 32768)       { W = w0; off = 0;      K = 128; N = 256; }
    else if (i < 98304)  { W = w1; off = 32768;  K = 256; N = 256; }
    else if (i < 163840) { W = w2; off = 98304;  K = 256; N = 256; }
    else if (i < 229376) { W = w3; off = 163840; K = 256; N = 256; }
    else if (i < 360448) { W = w4; off = 229376; K = 256; N = 512; }
    else                 { W = w5; off = 360448; K = 512; N = 512; }
    int j = i - off;
    int k = j / N, n = j % N;
    float x = W[j];
    __nv_bfloat16 h = __float2bfloat16(x);
    float r = x - __bfloat162float(h);
    hi[(size_t)off + (size_t)n * K + k] = h;
    lo[(size_t)off + (size_t)n * K + k] = __float2bfloat16(r);
}

// ---------------- embed: h = x @ W_embed + b; z = (1+eps0)*h ----------------
__global__ __launch_bounds__(256)
void embed_kernel(const float* __restrict__ x, const float* __restrict__ W,
                  const float* __restrict__ b, const float* __restrict__ eps,
                  float* __restrict__ h, float* __restrict__ z) {
    __shared__ float Ws[40 * 128];
    __shared__ float xs[32 * 40];
    __shared__ float bs[128];
    int tid = threadIdx.x;
    int n0 = blockIdx.x * 32;
    for (int i = tid; i < 40 * 128; i += 256) Ws[i] = W[i];
    if (tid < 128) bs[tid] = b[tid];
    for (int i = tid; i < 32 * 40; i += 256) {
        int n = n0 + (i / 40);
        xs[i] = (n < N_NODES) ? x[(size_t)n * 40 + (i % 40)] : 0.f;
    }
    __syncthreads();
    float s0 = 1.0f + eps[0];
    for (int i = tid; i < 32 * 128; i += 256) {
        int nl = i >> 7, col = i & 127;
        int n = n0 + nl;
        if (n >= N_NODES) continue;
        float acc = bs[col];
#pragma unroll
        for (int k = 0; k < 40; k++) acc = fmaf(xs[nl * 40 + k], Ws[k * 128 + col], acc);
        h[(size_t)n * 128 + col] = acc;
        z[(size_t)n * 128 + col] = s0 * acc;
    }
}

// ---------------- z[dst] += h[src] over edges (float4 REDG) --------
__global__ void scatter_kernel(const int* __restrict__ ei,
                               const float* __restrict__ h,
                               float* __restrict__ z,
                               int shift, int mask, int ntot) {
    int i = blockIdx.x * blockDim.x + threadIdx.x;
    if (i >= ntot) return;
    int e = i >> shift;
    int c = i & mask;
    int s = ei[e];
    int d = ei[N_EDGES + e];
    int D = (mask + 1) << 2;
    float4 v = *(const float4*)(h + (size_t)s * D + (size_t)c * 4);
    atomicAdd((float4*)(z + (size_t)d * D + (size_t)c * 4), v);
}

// ---------------- convert fp32 -> packed hi/lo (per 8-elem group) --------
__global__ void conv_kernel(const float4* __restrict__ z, uint4* __restrict__ zp,
                            int ngroups) {
    int i = blockIdx.x * blockDim.x + threadIdx.x;
    if (i >= ngroups) return;
    float4 a = z[2 * i], b = z[2 * i + 1];
    uint4 hi, lo;
    split2(a.x, a.y, hi.x, lo.x);
    split2(a.z, a.w, hi.y, lo.y);
    split2(b.x, b.y, hi.z, lo.z);
    split2(b.z, b.w, hi.w, lo.w);
    zp[2 * i] = hi;
    zp[2 * i + 1] = lo;
}

// ---------------- HMMA bf16x3 GEMM: C = act(A[M,K]@W[K,N]+bias) ----------------
// A packed hi/lo (pure cp.async), B pre-converted bf16 hi/lo [N][K].
// BM=128, BN=128, BK=32, 256 threads, 4x2 warps, warp tile 32x64, 3-stage.
// OMODE 0: C fp32 (+ optional scaled Z dual-write); OMODE 1: C packed hi/lo.
#define STG_A 0
#define STG_B_HI 16384
#define STG_B_LO 24576
#define STG_SIZE 32768
#define GEMM_SMEM (3 * STG_SIZE)

template <int OMODE>
__global__ __launch_bounds__(256, 2)
void mma_gemm(const char* __restrict__ Ab, const __nv_bfloat16* __restrict__ Bhi,
              const __nv_bfloat16* __restrict__ Blo, const float* __restrict__ bias,
              float* __restrict__ C, char* __restrict__ Cp,
              float* __restrict__ Z, const float* __restrict__ epsp, int zl,
              int M, int K, int N, int relu) {
    extern __shared__ char smem[];
    const int tid = threadIdx.x;
    const int lane = tid & 31;
    const int w = tid >> 5;
    const int wm = w & 3, wn = w >> 2;
    const int bm = blockIdx.y * 128;
    const int bn = blockIdx.x * 128;
    const uint32_t sbase = smem_u32(smem);

    float acc[2][8][4];
#pragma unroll
    for (int i = 0; i < 2; i++)
#pragma unroll
        for (int j = 0; j < 8; j++)
#pragma unroll
            for (int q = 0; q < 4; q++) acc[i][j][q] = 0.f;

    const int S = K >> 5;

    // A loader: 1024 16B chunks per stage; thread handles 4 (idx = tid + j*256)
    // idx -> local row rr = idx>>3, chunk q = idx&7 (q = kgroup*2 + hilo)
#define CP_STAGE(st, k0)                                                      \
    {                                                                         \
        uint32_t sa_ = sbase + (st) * STG_SIZE + STG_A;                       \
        uint32_t sb_ = sbase + (st) * STG_SIZE;                               \
        _Pragma("unroll")                                                     \
        for (int j_ = 0; j_ < 4; j_++) {                                      \
            int idx_ = tid + j_ * 256;                                        \
            int rr_ = idx_ >> 3, q_ = idx_ & 7;                               \
            size_t go_ = (size_t)(bm + rr_) * K * 4 + (size_t)(k0) * 4 +      \
                         (q_ >> 1) * 32 + (q_ & 1) * 16;                      \
            uint32_t so_ = (uint32_t)(rr_ * 128 + ((q_ ^ (rr_ & 7)) << 4));   \
            CP16(sa_ + so_, Ab + go_);                                        \
        }                                                                     \
        _Pragma("unroll")                                                     \
        for (int j_ = 0; j_ < 2; j_++) {                                      \
            int idx_ = tid + j_ * 256;                                        \
            int n_ = idx_ >> 2, g_ = idx_ & 3;                                \
            size_t go_ = (size_t)(bn + n_) * K + (k0) + g_ * 8;               \
            uint32_t so_ = SWZ(n_, g_);                                       \
            CP16(sb_ + STG_B_HI + so_, Bhi + go_);                            \
            CP16(sb_ + STG_B_LO + so_, Blo + go_);                            \
        }                                                                     \
        asm volatile("cp.async.commit_group;" ::: "memory");                  \
    }

    // ---- prologue: stages 0 and 1 in flight ----
    CP_STAGE(0, 0);
    CP_STAGE(1, 32);
    asm volatile("cp.async.wait_group 1;" ::: "memory");
    __syncthreads();

    // per-lane ldmatrix bases
    uint32_t a_row128[2], a_rkey[2];
#pragma unroll
    for (int mt = 0; mt < 2; mt++) {
        int row = wm * 32 + mt * 16 + (lane & 15);
        a_row128[mt] = (uint32_t)(row * 128);
        a_rkey[mt] = (uint32_t)(row & 7);
    }
    const uint32_t a_kbit = (lane >> 4) & 1;
    uint32_t b_base[4], b_key[4];
#pragma unroll
    for (int np = 0; np < 4; np++) {
        int row = wn * 64 + np * 16 + ((lane >> 4) & 1) * 8 + (lane & 7);
        b_base[np] = (uint32_t)(row * 64);
        b_key[np] = (uint32_t)((row >> 1) & 3);
    }
    const uint32_t b_c16_bit = (lane >> 3) & 1;

    int cst = 0;
    for (int s = 0; s < S; s++) {
        if (s + 2 < S) CP_STAGE((s + 2) % 3, (s + 2) << 5);

        const uint32_t sg = sbase + cst * STG_SIZE;
#pragma unroll
        for (int kh = 0; kh < 2; kh++) {
            uint32_t ahi[2][4], alo[2][4];
#pragma unroll
            for (int mt = 0; mt < 2; mt++) {
                uint32_t q = (uint32_t)(kh * 2 + a_kbit) * 2;   // hi chunk
                uint32_t base = sg + STG_A + a_row128[mt];
                LDM4(ahi[mt], base + ((q ^ a_rkey[mt]) << 4));
                LDM4(alo[mt], base + (((q + 1) ^ a_rkey[mt]) << 4));
            }
#pragma unroll
            for (int np = 0; np < 4; np++) {
                uint32_t c16 = (uint32_t)(kh * 2) + b_c16_bit;
                uint32_t bd = sg + b_base[np] + ((c16 ^ b_key[np]) << 4);
                uint32_t bh[4], bl[4];
                LDM4(bh, bd + STG_B_HI);
                LDM4(bl, bd + STG_B_LO);
#pragma unroll
                for (int mt = 0; mt < 2; mt++) {
                    MMA16816(acc[mt][np * 2], ahi[mt], bh[0], bh[1]);
                    MMA16816(acc[mt][np * 2], ahi[mt], bl[0], bl[1]);
                    MMA16816(acc[mt][np * 2], alo[mt], bh[0], bh[1]);
                    MMA16816(acc[mt][np * 2 + 1], ahi[mt], bh[2], bh[3]);
                    MMA16816(acc[mt][np * 2 + 1], ahi[mt], bl[2], bl[3]);
                    MMA16816(acc[mt][np * 2 + 1], alo[mt], bh[2], bh[3]);
                }
            }
        }

        if (s + 1 < S) {
            if (s + 2 < S) {
                asm volatile("cp.async.wait_group 1;" ::: "memory");
            } else {
                asm volatile("cp.async.wait_group 0;" ::: "memory");
            }
            __syncthreads();
            cst = (s + 1) % 3;
        }
    }

    // ---- epilogue ----
    float zs = 0.f;
    if (OMODE == 0 && Z) zs = 1.0f + epsp[zl];
#pragma unroll
    for (int mt = 0; mt < 2; mt++) {
        int r0 = bm + wm * 32 + mt * 16 + (lane >> 2);
#pragma unroll
        for (int nt = 0; nt < 8; nt++) {
            int col = bn + wn * 64 + nt * 8 + (lane & 3) * 2;
            float b0 = bias[col], b1 = bias[col + 1];
            float v0 = acc[mt][nt][0] + b0, v1 = acc[mt][nt][1] + b1;
            float v2 = acc[mt][nt][2] + b0, v3 = acc[mt][nt][3] + b1;
            if (relu) {
                v0 = fmaxf(v0, 0.f); v1 = fmaxf(v1, 0.f);
                v2 = fmaxf(v2, 0.f); v3 = fmaxf(v3, 0.f);
            }
            if (OMODE == 0) {
                if (r0 < M) {
                    *(float2*)(C + (size_t)r0 * N + col) = make_float2(v0, v1);
                    if (Z) *(float2*)(Z + (size_t)r0 * N + col) =
                        make_float2(zs * v0, zs * v1);
                }
                if (r0 + 8 < M) {
                    *(float2*)(C + (size_t)(r0 + 8) * N + col) = make_float2(v2, v3);
                    if (Z) *(float2*)(Z + (size_t)(r0 + 8) * N + col) =
                        make_float2(zs * v2, zs * v3);
                }
            } else {
                uint32_t h01, l01, h23, l23;
                split2(v0, v1, h01, l01);
                split2(v2, v3, h23, l23);
                size_t base = (size_t)r0 * N * 4 + (size_t)(col >> 3) * 32 +
                              (col & 7) * 2;
                if (r0 < M) {
                    *(uint32_t*)(Cp + base) = h01;
                    *(uint32_t*)(Cp + base + 16) = l01;
                }
                if (r0 + 8 < M) {
                    size_t b2_ = base + (size_t)8 * N * 4;
                    *(uint32_t*)(Cp + b2_) = h23;
                    *(uint32_t*)(Cp + b2_ + 16) = l23;
                }
            }
        }
    }
#undef CP_STAGE
}

// ---------------- fused pool + task head (batch is sorted) ----------------
__device__ __forceinline__ int lowb(const int* __restrict__ a, int n, int v) {
    int lo = 0, hi = n;
    while (lo < hi) {
        int m = (lo + hi) >> 1;
        if (a[m] < v) lo = m + 1; else hi = m;
    }
    return lo;
}

__global__ __launch_bounds__(128)
void pool_task_kernel(const int* __restrict__ batch, const float* __restrict__ h,
                      const float* __restrict__ W, const float* __restrict__ b,
                      float* __restrict__ out) {
    int g = blockIdx.x;
    int t = threadIdx.x;  // 128
    int start = lowb(batch, N_NODES, g);
    int end = lowb(batch, N_NODES, g + 1);
    float4 acc = make_float4(0.f, 0.f, 0.f, 0.f);
    for (int n = start; n < end; n++) {
        float4 v = ((const float4*)(h + (size_t)n * 512))[t];
        acc.x += v.x; acc.y += v.y; acc.z += v.z; acc.w += v.w;
    }
    float4 wv = ((const float4*)W)[t];
    float d = acc.x * wv.x + acc.y * wv.y + acc.z * wv.z + acc.w * wv.w;
#pragma unroll
    for (int o = 16; o > 0; o >>= 1) d += __shfl_xor_sync(0xffffffffu, d, o);
    __shared__ float s[4];
    if ((t & 31) == 0) s[t >> 5] = d;
    __syncthreads();
    if (t == 0) out[g] = s[0] + s[1] + s[2] + s[3] + b[0];
}

// ---------------- launch ----------------
extern "C" void kernel_launch(void* const* d_in, const int* in_sizes, int n_in,
                              void* d_out, int out_size) {
    const float* x       = (const float*)d_in[0];
    const int*   ei      = (const int*)d_in[1];
    const int*   batch   = (const int*)d_in[2];
    const float* W_embed = (const float*)d_in[3];
    const float* b_embed = (const float*)d_in[4];
    const float* eps     = (const float*)d_in[5];
    const float* W1[3] = {(const float*)d_in[6],  (const float*)d_in[10], (const float*)d_in[14]};
    const float* b1[3] = {(const float*)d_in[7],  (const float*)d_in[11], (const float*)d_in[15]};
    const float* W2[3] = {(const float*)d_in[8],  (const float*)d_in[12], (const float*)d_in[16]};
    const float* b2[3] = {(const float*)d_in[9],  (const float*)d_in[13], (const float*)d_in[17]};
    const float* W_task = (const float*)d_in[18];
    const float* b_task = (const float*)d_in[19];
    float* out = (float*)d_out;

    float *h, *z;
    uint32_t *zp, *tp;
    __nv_bfloat16 *whi, *wlo;
    cudaGetSymbolAddress((void**)&h, g_h);
    cudaGetSymbolAddress((void**)&z, g_z);
    cudaGetSymbolAddress((void**)&zp, g_zp);
    cudaGetSymbolAddress((void**)&tp, g_tp);
    cudaGetSymbolAddress((void**)&whi, g_whi);
    cudaGetSymbolAddress((void**)&wlo, g_wlo);

    cudaFuncSetAttribute(mma_gemm<0>, cudaFuncAttributeMaxDynamicSharedMemorySize, GEMM_SMEM);
    cudaFuncSetAttribute(mma_gemm<1>, cudaFuncAttributeMaxDynamicSharedMemorySize, GEMM_SMEM);

    prep_all<<<(622592 + 255) / 256, 256>>>(W1[0], W2[0], W1[1], W2[1], W1[2], W2[2],
                                            whi, wlo);
    embed_kernel<<<(N_NODES + 31) / 32, 256>>>(x, W_embed, b_embed, eps, h, z);

    const size_t woff[6] = {0, 32768, 98304, 163840, 229376, 360448};
    const int Din[3]  = {128, 256, 256};
    const int Dmid[3] = {256, 256, 512};
    const int Dout[3] = {256, 256, 512};
    const int MT = M_PAD / 128;   // 782

    for (int l = 0; l < 3; l++) {
        int D = Din[l];

        int shift = (D == 128) ? 5 : 6;
        int mask = (1 << shift) - 1;
        int ntot = N_EDGES << shift;
        scatter_kernel<<<(ntot + 255) / 256, 256>>>(ei, h, z, shift, mask, ntot);

        int ngroups = N_NODES * D / 8;
        conv_kernel<<<(ngroups + 255) / 256, 256>>>((const float4*)z, (uint4*)zp,
                                                    ngroups);

        // GEMM1: A = packed z -> packed t, relu
        mma_gemm<1><<<dim3(Dmid[l] / 128, MT), 256, GEMM_SMEM>>>(
            (const char*)zp, whi + woff[2 * l], wlo + woff[2 * l], b1[l],
            nullptr, (char*)tp, nullptr, nullptr, 0,
            N_NODES, D, Dmid[l], 1);

        // GEMM2: A = packed t -> h fp32 (+ scaled z for l<2), relu unless last
        mma_gemm<0><<<dim3(Dout[l] / 128, MT), 256, GEMM_SMEM>>>(
            (const char*)tp, whi + woff[2 * l + 1], wlo + woff[2 * l + 1], b2[l],
            h, nullptr, (l < 2) ? z : nullptr, eps, l + 1,
            N_NODES, Dmid[l], Dout[l], (l < 2) ? 1 : 0);
    }

    pool_task_kernel<<<N_GRAPHS, 128>>>(batch, h, W_task, b_task, out);
}

// round 10
// speedup vs baseline: 1.3999x; 1.1640x over previous
#include <cuda_runtime.h>
#include <cuda_bf16.h>
#include <cstdint>
#include <cstddef>

#define N_NODES 100000
#define M_PAD   100096
#define N_EDGES 300000
#define N_GRAPHS 2048

// ---------------- scratch (no allocations allowed) ----------------
__device__ __align__(256) float g_h[(size_t)N_NODES * 512];
__device__ __align__(256) uint32_t g_zp[(size_t)M_PAD * 256];   // packed z (hi/lo)
__device__ __align__(256) uint32_t g_tp[(size_t)M_PAD * 512];   // packed t (hi/lo)
__device__ __align__(256) __nv_bfloat16 g_whi[622592];
__device__ __align__(256) __nv_bfloat16 g_wlo[622592];
// CSR scratch
__device__ int g_counts[N_NODES];
__device__ int g_off[N_NODES];
__device__ int g_cur[N_NODES];
__device__ int g_bsum[512];
__device__ int g_esrc[N_EDGES];

// packed A layout: element (r, c) of [M, K]:
//   byte r*K*4 + (c>>3)*32 + (c&7)*2 (hi);  +16 (lo)

// ---------------- helpers ----------------
__device__ __forceinline__ uint32_t smem_u32(const void* p) {
    uint32_t a;
    asm("{ .reg .u64 t; cvta.to.shared.u64 t, %1; cvt.u32.u64 %0, t; }"
        : "=r"(a) : "l"(p));
    return a;
}

#define LDM4(r, addr)                                                         \
    asm volatile("ldmatrix.sync.aligned.m8n8.x4.shared.b16 {%0,%1,%2,%3}, [%4];" \
                 : "=r"((r)[0]), "=r"((r)[1]), "=r"((r)[2]), "=r"((r)[3])     \
                 : "r"(addr))

#define MMA16816(c, a, b0, b1)                                                \
    asm volatile("mma.sync.aligned.m16n8k16.row.col.f32.bf16.bf16.f32 "        \
                 "{%0,%1,%2,%3}, {%4,%5,%6,%7}, {%8,%9}, {%0,%1,%2,%3};"       \
                 : "+f"((c)[0]), "+f"((c)[1]), "+f"((c)[2]), "+f"((c)[3])      \
                 : "r"((a)[0]), "r"((a)[1]), "r"((a)[2]), "r"((a)[3]),         \
                   "r"(b0), "r"(b1))

#define CP16(saddr, gaddr)                                                    \
    asm volatile("cp.async.cg.shared.global [%0], [%1], 16;" ::               \
                 "r"(saddr), "l"(gaddr))

#define SWZ(row, c16) ((uint32_t)((row) * 64 + ((((c16) ^ (((row) >> 1) & 3))) << 4)))

__device__ __forceinline__ void split2(float a, float b, uint32_t& hw, uint32_t& lw) {
    __nv_bfloat162 hp = __floats2bfloat162_rn(a, b);
    float2 hf = __bfloat1622float2(hp);
    __nv_bfloat162 lp = __floats2bfloat162_rn(a - hf.x, b - hf.y);
    hw = *reinterpret_cast<uint32_t*>(&hp);
    lw = *reinterpret_cast<uint32_t*>(&lp);
}

// ---------------- fused: weight prep + embed + zero counts ----------------
#define PREP_BLKS 2432
#define EMB_BLKS  3125
#define ZERO_BLKS 391

__global__ __launch_bounds__(256)
void fused_prep(const float* __restrict__ w0, const float* __restrict__ w1,
                const float* __restrict__ w2, const float* __restrict__ w3,
                const float* __restrict__ w4, const float* __restrict__ w5,
                __nv_bfloat16* __restrict__ hi, __nv_bfloat16* __restrict__ lo,
                const float* __restrict__ x, const float* __restrict__ We,
                const float* __restrict__ be, float* __restrict__ h,
                int* __restrict__ counts) {
    int bid = blockIdx.x;
    int tid = threadIdx.x;
    if (bid < PREP_BLKS) {
        int i = bid * 256 + tid;
        if (i >= 622592) return;
        const float* W;
        int off, K, N;
        if (i < 32768)       { W = w0; off = 0;      K = 128; N = 256; }
        else if (i < 98304)  { W = w1; off = 32768;  K = 256; N = 256; }
        else if (i < 163840) { W = w2; off = 98304;  K = 256; N = 256; }
        else if (i < 229376) { W = w3; off = 163840; K = 256; N = 256; }
        else if (i < 360448) { W = w4; off = 229376; K = 256; N = 512; }
        else                 { W = w5; off = 360448; K = 512; N = 512; }
        int j = i - off;
        int k = j / N, n = j % N;
        float v = W[j];
        __nv_bfloat16 hh = __float2bfloat16(v);
        float r = v - __bfloat162float(hh);
        hi[(size_t)off + (size_t)n * K + k] = hh;
        lo[(size_t)off + (size_t)n * K + k] = __float2bfloat16(r);
    } else if (bid < PREP_BLKS + EMB_BLKS) {
        __shared__ float Ws[40 * 128];
        __shared__ float xs[32 * 40];
        __shared__ float bs[128];
        int n0 = (bid - PREP_BLKS) * 32;
        for (int i = tid; i < 40 * 128; i += 256) Ws[i] = We[i];
        if (tid < 128) bs[tid] = be[tid];
        for (int i = tid; i < 32 * 40; i += 256) {
            int n = n0 + (i / 40);
            xs[i] = (n < N_NODES) ? x[(size_t)n * 40 + (i % 40)] : 0.f;
        }
        __syncthreads();
        for (int i = tid; i < 32 * 128; i += 256) {
            int nl = i >> 7, col = i & 127;
            int n = n0 + nl;
            if (n >= N_NODES) continue;
            float acc = bs[col];
#pragma unroll
            for (int k = 0; k < 40; k++)
                acc = fmaf(xs[nl * 40 + k], Ws[k * 128 + col], acc);
            h[(size_t)n * 128 + col] = acc;
        }
    } else {
        int i = (bid - PREP_BLKS - EMB_BLKS) * 256 + tid;
        if (i < N_NODES) counts[i] = 0;
    }
}

// ---------------- CSR build ----------------
__global__ void hist_kernel(const int* __restrict__ ei, int* __restrict__ counts) {
    int e = blockIdx.x * blockDim.x + threadIdx.x;
    if (e >= N_EDGES) return;
    atomicAdd(&counts[ei[N_EDGES + e]], 1);
}

__global__ void scan1_kernel(const int* __restrict__ counts, int* __restrict__ off,
                             int* __restrict__ bsum) {
    int t = threadIdx.x;
    int idx = blockIdx.x * 256 + t;
    int c = (idx < N_NODES) ? counts[idx] : 0;
    int v = c;
#pragma unroll
    for (int o = 1; o < 32; o <<= 1) {
        int u = __shfl_up_sync(0xffffffffu, v, o);
        if ((t & 31) >= o) v += u;
    }
    __shared__ int ws[8];
    if ((t & 31) == 31) ws[t >> 5] = v;
    __syncthreads();
    if (t < 8) {
        int wv = ws[t];
#pragma unroll
        for (int o = 1; o < 8; o <<= 1) {
            int u = __shfl_up_sync(0xffu, wv, o);
            if (t >= o) wv += u;
        }
        ws[t] = wv;
    }
    __syncthreads();
    int base = (t >= 32) ? ws[(t >> 5) - 1] : 0;
    int inc = v + base;
    if (idx < N_NODES) off[idx] = inc - c;
    if (t == 255) bsum[blockIdx.x] = inc;
}

__global__ void scan2_kernel(int* __restrict__ off, const int* __restrict__ bsum,
                             int* __restrict__ cursor, int nblk) {
    __shared__ int sp[256];
    int t = threadIdx.x;
    int s = 0;
    for (int j = t; j < nblk; j += 256)
        if (j < (int)blockIdx.x) s += bsum[j];
    sp[t] = s;
    __syncthreads();
#pragma unroll
    for (int o = 128; o > 0; o >>= 1) {
        if (t < o) sp[t] += sp[t + o];
        __syncthreads();
    }
    int prefix = sp[0];
    int idx = blockIdx.x * 256 + t;
    if (idx < N_NODES) {
        int v = off[idx] + prefix;
        off[idx] = v;
        cursor[idx] = v;
    }
}

__global__ void fill_kernel(const int* __restrict__ ei, int* __restrict__ cursor,
                            int* __restrict__ esrc) {
    int e = blockIdx.x * blockDim.x + threadIdx.x;
    if (e >= N_EDGES) return;
    int s = ei[e];
    int d = ei[N_EDGES + e];
    int slot = atomicAdd(&cursor[d], 1);
    esrc[slot] = s;
}

// ---------------- agg + pack: z = (1+eps)*h[n] + sum h[src], packed hi/lo ----
// LPN lanes per node (D/8); block 256 threads.
template <int LPN>
__global__ __launch_bounds__(256)
void agg_pack(const int* __restrict__ off, const int* __restrict__ cur,
              const int* __restrict__ esrc, const float* __restrict__ h,
              const float* __restrict__ eps, int l, uint4* __restrict__ zp) {
    const int D = LPN * 8;
    int nid = blockIdx.x * (256 / LPN) + threadIdx.x / LPN;
    int gl = threadIdx.x % LPN;
    if (nid >= N_NODES) return;
    float sc = 1.f + eps[l];
    const float4* hp = (const float4*)(h + (size_t)nid * D) + gl * 2;
    float4 a = hp[0], b = hp[1];
    a.x *= sc; a.y *= sc; a.z *= sc; a.w *= sc;
    b.x *= sc; b.y *= sc; b.z *= sc; b.w *= sc;
    int s = off[nid], e = cur[nid];
    for (int i = s; i < e; i++) {
        int r = esrc[i];
        const float4* q = (const float4*)(h + (size_t)r * D) + gl * 2;
        float4 u = q[0], v = q[1];
        a.x += u.x; a.y += u.y; a.z += u.z; a.w += u.w;
        b.x += v.x; b.y += v.y; b.z += v.z; b.w += v.w;
    }
    uint4 hi, lo;
    split2(a.x, a.y, hi.x, lo.x);
    split2(a.z, a.w, hi.y, lo.y);
    split2(b.x, b.y, hi.z, lo.z);
    split2(b.z, b.w, hi.w, lo.w);
    size_t base = (size_t)nid * (D / 4) + gl * 2;
    zp[base] = hi;
    zp[base + 1] = lo;
}

// ---------------- HMMA bf16x3 GEMM (pure cp.async A, packed) ----------------
#define STG_A 0
#define STG_B_HI 16384
#define STG_B_LO 24576
#define STG_SIZE 32768
#define GEMM_SMEM (3 * STG_SIZE)

template <int OMODE>   // 0: C fp32; 1: Cp packed hi/lo
__global__ __launch_bounds__(256, 2)
void mma_gemm(const char* __restrict__ Ab, const __nv_bfloat16* __restrict__ Bhi,
              const __nv_bfloat16* __restrict__ Blo, const float* __restrict__ bias,
              float* __restrict__ C, char* __restrict__ Cp,
              int M, int K, int N, int relu) {
    extern __shared__ char smem[];
    const int tid = threadIdx.x;
    const int lane = tid & 31;
    const int w = tid >> 5;
    const int wm = w & 3, wn = w >> 2;
    const int bm = blockIdx.y * 128;
    const int bn = blockIdx.x * 128;
    const uint32_t sbase = smem_u32(smem);

    float acc[2][8][4];
#pragma unroll
    for (int i = 0; i < 2; i++)
#pragma unroll
        for (int j = 0; j < 8; j++)
#pragma unroll
            for (int q = 0; q < 4; q++) acc[i][j][q] = 0.f;

    const int S = K >> 5;

#define CP_STAGE(st, k0)                                                      \
    {                                                                         \
        uint32_t sa_ = sbase + (st) * STG_SIZE + STG_A;                       \
        uint32_t sb_ = sbase + (st) * STG_SIZE;                               \
        _Pragma("unroll")                                                     \
        for (int j_ = 0; j_ < 4; j_++) {                                      \
            int idx_ = tid + j_ * 256;                                        \
            int rr_ = idx_ >> 3, q_ = idx_ & 7;                               \
            size_t go_ = (size_t)(bm + rr_) * K * 4 + (size_t)(k0) * 4 +      \
                         (q_ >> 1) * 32 + (q_ & 1) * 16;                      \
            uint32_t so_ = (uint32_t)(rr_ * 128 + ((q_ ^ (rr_ & 7)) << 4));   \
            CP16(sa_ + so_, Ab + go_);                                        \
        }                                                                     \
        _Pragma("unroll")                                                     \
        for (int j_ = 0; j_ < 2; j_++) {                                      \
            int idx_ = tid + j_ * 256;                                        \
            int n_ = idx_ >> 2, g_ = idx_ & 3;                                \
            size_t go_ = (size_t)(bn + n_) * K + (k0) + g_ * 8;               \
            uint32_t so_ = SWZ(n_, g_);                                       \
            CP16(sb_ + STG_B_HI + so_, Bhi + go_);                            \
            CP16(sb_ + STG_B_LO + so_, Blo + go_);                            \
        }                                                                     \
        asm volatile("cp.async.commit_group;" ::: "memory");                  \
    }

    CP_STAGE(0, 0);
    CP_STAGE(1, 32);
    asm volatile("cp.async.wait_group 1;" ::: "memory");
    __syncthreads();

    uint32_t a_row128[2], a_rkey[2];
#pragma unroll
    for (int mt = 0; mt < 2; mt++) {
        int row = wm * 32 + mt * 16 + (lane & 15);
        a_row128[mt] = (uint32_t)(row * 128);
        a_rkey[mt] = (uint32_t)(row & 7);
    }
    const uint32_t a_kbit = (lane >> 4) & 1;
    uint32_t b_base[4], b_key[4];
#pragma unroll
    for (int np = 0; np < 4; np++) {
        int row = wn * 64 + np * 16 + ((lane >> 4) & 1) * 8 + (lane & 7);
        b_base[np] = (uint32_t)(row * 64);
        b_key[np] = (uint32_t)((row >> 1) & 3);
    }
    const uint32_t b_c16_bit = (lane >> 3) & 1;

    int cst = 0;
    for (int s = 0; s < S; s++) {
        if (s + 2 < S) CP_STAGE((s + 2) % 3, (s + 2) << 5);

        const uint32_t sg = sbase + cst * STG_SIZE;
#pragma unroll
        for (int kh = 0; kh < 2; kh++) {
            uint32_t ahi[2][4], alo[2][4];
#pragma unroll
            for (int mt = 0; mt < 2; mt++) {
                uint32_t q = (uint32_t)(kh * 2 + a_kbit) * 2;
                uint32_t base = sg + STG_A + a_row128[mt];
                LDM4(ahi[mt], base + ((q ^ a_rkey[mt]) << 4));
                LDM4(alo[mt], base + (((q + 1) ^ a_rkey[mt]) << 4));
            }
#pragma unroll
            for (int np = 0; np < 4; np++) {
                uint32_t c16 = (uint32_t)(kh * 2) + b_c16_bit;
                uint32_t bd = sg + b_base[np] + ((c16 ^ b_key[np]) << 4);
                uint32_t bh[4], bl[4];
                LDM4(bh, bd + STG_B_HI);
                LDM4(bl, bd + STG_B_LO);
#pragma unroll
                for (int mt = 0; mt < 2; mt++) {
                    MMA16816(acc[mt][np * 2], ahi[mt], bh[0], bh[1]);
                    MMA16816(acc[mt][np * 2], ahi[mt], bl[0], bl[1]);
                    MMA16816(acc[mt][np * 2], alo[mt], bh[0], bh[1]);
                    MMA16816(acc[mt][np * 2 + 1], ahi[mt], bh[2], bh[3]);
                    MMA16816(acc[mt][np * 2 + 1], ahi[mt], bl[2], bl[3]);
                    MMA16816(acc[mt][np * 2 + 1], alo[mt], bh[2], bh[3]);
                }
            }
        }

        if (s + 1 < S) {
            if (s + 2 < S) {
                asm volatile("cp.async.wait_group 1;" ::: "memory");
            } else {
                asm volatile("cp.async.wait_group 0;" ::: "memory");
            }
            __syncthreads();
            cst = (s + 1) % 3;
        }
    }

    // ---- epilogue ----
#pragma unroll
    for (int mt = 0; mt < 2; mt++) {
        int r0 = bm + wm * 32 + mt * 16 + (lane >> 2);
#pragma unroll
        for (int nt = 0; nt < 8; nt++) {
            int col = bn + wn * 64 + nt * 8 + (lane & 3) * 2;
            float b0 = bias[col], b1 = bias[col + 1];
            float v0 = acc[mt][nt][0] + b0, v1 = acc[mt][nt][1] + b1;
            float v2 = acc[mt][nt][2] + b0, v3 = acc[mt][nt][3] + b1;
            if (relu) {
                v0 = fmaxf(v0, 0.f); v1 = fmaxf(v1, 0.f);
                v2 = fmaxf(v2, 0.f); v3 = fmaxf(v3, 0.f);
            }
            if (OMODE == 0) {
                if (r0 < M) *(float2*)(C + (size_t)r0 * N + col) = make_float2(v0, v1);
                if (r0 + 8 < M) *(float2*)(C + (size_t)(r0 + 8) * N + col) = make_float2(v2, v3);
            } else {
                uint32_t h01, l01, h23, l23;
                split2(v0, v1, h01, l01);
                split2(v2, v3, h23, l23);
                size_t base = (size_t)r0 * N * 4 + (size_t)(col >> 3) * 32 +
                              (col & 7) * 2;
                if (r0 < M) {
                    *(uint32_t*)(Cp + base) = h01;
                    *(uint32_t*)(Cp + base + 16) = l01;
                }
                if (r0 + 8 < M) {
                    size_t b2_ = base + (size_t)8 * N * 4;
                    *(uint32_t*)(Cp + b2_) = h23;
                    *(uint32_t*)(Cp + b2_ + 16) = l23;
                }
            }
        }
    }
#undef CP_STAGE
}

// ---------------- fused pool + task head (batch is sorted) ----------------
__device__ __forceinline__ int lowb(const int* __restrict__ a, int n, int v) {
    int lo = 0, hi = n;
    while (lo < hi) {
        int m = (lo + hi) >> 1;
        if (a[m] < v) lo = m + 1; else hi = m;
    }
    return lo;
}

__global__ __launch_bounds__(128)
void pool_task_kernel(const int* __restrict__ batch, const float* __restrict__ h,
                      const float* __restrict__ W, const float* __restrict__ b,
                      float* __restrict__ out) {
    int g = blockIdx.x;
    int t = threadIdx.x;
    int start = lowb(batch, N_NODES, g);
    int end = lowb(batch, N_NODES, g + 1);
    float4 acc = make_float4(0.f, 0.f, 0.f, 0.f);
    for (int n = start; n < end; n++) {
        float4 v = ((const float4*)(h + (size_t)n * 512))[t];
        acc.x += v.x; acc.y += v.y; acc.z += v.z; acc.w += v.w;
    }
    float4 wv = ((const float4*)W)[t];
    float d = acc.x * wv.x + acc.y * wv.y + acc.z * wv.z + acc.w * wv.w;
#pragma unroll
    for (int o = 16; o > 0; o >>= 1) d += __shfl_xor_sync(0xffffffffu, d, o);
    __shared__ float s[4];
    if ((t & 31) == 0) s[t >> 5] = d;
    __syncthreads();
    if (t == 0) out[g] = s[0] + s[1] + s[2] + s[3] + b[0];
}

// ---------------- launch ----------------
extern "C" void kernel_launch(void* const* d_in, const int* in_sizes, int n_in,
                              void* d_out, int out_size) {
    const float* x       = (const float*)d_in[0];
    const int*   ei      = (const int*)d_in[1];
    const int*   batch   = (const int*)d_in[2];
    const float* W_embed = (const float*)d_in[3];
    const float* b_embed = (const float*)d_in[4];
    const float* eps     = (const float*)d_in[5];
    const float* W1[3] = {(const float*)d_in[6],  (const float*)d_in[10], (const float*)d_in[14]};
    const float* b1[3] = {(const float*)d_in[7],  (const float*)d_in[11], (const float*)d_in[15]};
    const float* W2[3] = {(const float*)d_in[8],  (const float*)d_in[12], (const float*)d_in[16]};
    const float* b2[3] = {(const float*)d_in[9],  (const float*)d_in[13], (const float*)d_in[17]};
    const float* W_task = (const float*)d_in[18];
    const float* b_task = (const float*)d_in[19];
    float* out = (float*)d_out;

    float *h;
    uint32_t *zp, *tp;
    __nv_bfloat16 *whi, *wlo;
    int *counts, *off, *cur, *bsum, *esrc;
    cudaGetSymbolAddress((void**)&h, g_h);
    cudaGetSymbolAddress((void**)&zp, g_zp);
    cudaGetSymbolAddress((void**)&tp, g_tp);
    cudaGetSymbolAddress((void**)&whi, g_whi);
    cudaGetSymbolAddress((void**)&wlo, g_wlo);
    cudaGetSymbolAddress((void**)&counts, g_counts);
    cudaGetSymbolAddress((void**)&off, g_off);
    cudaGetSymbolAddress((void**)&cur, g_cur);
    cudaGetSymbolAddress((void**)&bsum, g_bsum);
    cudaGetSymbolAddress((void**)&esrc, g_esrc);

    cudaFuncSetAttribute(mma_gemm<0>, cudaFuncAttributeMaxDynamicSharedMemorySize, GEMM_SMEM);
    cudaFuncSetAttribute(mma_gemm<1>, cudaFuncAttributeMaxDynamicSharedMemorySize, GEMM_SMEM);

    // 0: fused weight prep + embed + zero counts
    fused_prep<<<PREP_BLKS + EMB_BLKS + ZERO_BLKS, 256>>>(
        W1[0], W2[0], W1[1], W2[1], W1[2], W2[2], whi, wlo,
        x, W_embed, b_embed, h, counts);

    // CSR build (once; edges are layer-invariant)
    const int NBLK = (N_NODES + 255) / 256;   // 391
    hist_kernel<<<(N_EDGES + 255) / 256, 256>>>(ei, counts);
    scan1_kernel<<<NBLK, 256>>>(counts, off, bsum);
    scan2_kernel<<<NBLK, 256>>>(off, bsum, cur, NBLK);
    fill_kernel<<<(N_EDGES + 255) / 256, 256>>>(ei, cur, esrc);

    const size_t woff[6] = {0, 32768, 98304, 163840, 229376, 360448};
    const int Din[3]  = {128, 256, 256};
    const int Dmid[3] = {256, 256, 512};
    const int Dout[3] = {256, 256, 512};
    const int MT = M_PAD / 128;   // 782

    for (int l = 0; l < 3; l++) {
        int D = Din[l];

        if (D == 128)
            agg_pack<16><<<(N_NODES + 15) / 16, 256>>>(off, cur, esrc, h, eps, l,
                                                       (uint4*)zp);
        else
            agg_pack<32><<<(N_NODES + 7) / 8, 256>>>(off, cur, esrc, h, eps, l,
                                                     (uint4*)zp);

        // GEMM1: packed z -> packed t, relu
        mma_gemm<1><<<dim3(Dmid[l] / 128, MT), 256, GEMM_SMEM>>>(
            (const char*)zp, whi + woff[2 * l], wlo + woff[2 * l], b1[l],
            nullptr, (char*)tp, N_NODES, D, Dmid[l], 1);

        // GEMM2: packed t -> h fp32, relu unless last
        mma_gemm<0><<<dim3(Dout[l] / 128, MT), 256, GEMM_SMEM>>>(
            (const char*)tp, whi + woff[2 * l + 1], wlo + woff[2 * l + 1], b2[l],
            h, nullptr, N_NODES, Dmid[l], Dout[l], (l < 2) ? 1 : 0);
    }

    pool_task_kernel<<<N_GRAPHS, 128>>>(batch, h, W_task, b_task, out);
}